// round 10
// baseline (speedup 1.0000x reference)
#include <cuda_runtime.h>
#include <cuda_fp16.h>
#include <cstdint>

#define NFFT 16384
#define DIML 8192
#define DIMD 1024
#define NT   512        // 512 threads, 2 groups of 16 elements per thread

// conflict-killing swizzle for sA: XOR low 4 bits with bits[7:4] (self-inverse)
#define SWZ(i) ((i) ^ (((i) >> 4) & 15))

// smem layout (bytes)
//   sA     : float2[16384]   @ 0        (131072)
//   sH     : half2 [16384]   @ 131072   (65536)
//   sA1024 : float2[1024]    @ 196608   (8192)   W^j,      j<1024 (W = W_16384)
//   sB256  : float2[256]     @ 204800   (2048)   W_256^j,  j<256   (stage-64 tw)
//   sW1024 : float2[256]     @ 206848   (2048)   W_1024^j, j<256   (stage-256 tw)
//   sT16   : float2[16]      @ 208896   (128)    W_64^j            (stage-16 tw)
//   sT4    : float2[4]       @ 209024   (32)     W_16^j == W^{1024j} (stage-4 + K4)
#define SMEM_BYTES 209056

// ---------------- device scratch ----------------
__device__ float2 g_xt[(size_t)DIMD * DIML];       // transposed x, batches packed
__device__ float  g_ht[(size_t)DIMD * DIML];       // transposed h
__device__ float2 g_ys[(size_t)DIMD * DIML];       // transposed scaled output

__device__ __forceinline__ float2 cmul(float2 a, float2 b) {
    return make_float2(a.x * b.x - a.y * b.y, a.x * b.y + a.y * b.x);
}
__device__ __forceinline__ float2 cconj(float2 a) { return make_float2(a.x, -a.y); }
__device__ __forceinline__ float2 cadd(float2 a, float2 b) { return make_float2(a.x + b.x, a.y + b.y); }
__device__ __forceinline__ float2 csub(float2 a, float2 b) { return make_float2(a.x - b.x, a.y - b.y); }

// DIF forward radix-4 butterfly (in place)
__device__ __forceinline__ void bfly(float2& a, float2& b, float2& c, float2& d) {
    float2 t0 = cadd(a, c), t1 = csub(a, c), t2 = cadd(b, d), t3 = csub(b, d);
    float2 t3s = make_float2(t3.y, -t3.x);     // -i * t3
    a = cadd(t0, t2);
    c = csub(t0, t2);
    b = cadd(t1, t3s);
    d = csub(t1, t3s);
}
// inverse radix-4 butterfly (unnormalized)
__device__ __forceinline__ void ibfly(float2& a, float2& b, float2& c, float2& d) {
    float2 u0 = cadd(a, c), u1 = csub(a, c), u2 = cadd(b, d), u3 = csub(b, d);
    float2 u3s = make_float2(u3.y, -u3.x);
    a = cadd(u0, u2);
    c = csub(u0, u2);
    b = csub(u1, u3s);
    d = cadd(u1, u3s);
}
__device__ __forceinline__ void tw3w(float2& b, float2& c, float2& d,
                                     float2 w1, float2 w2, float2 w3) {
    b = cmul(b, w1); c = cmul(c, w2); d = cmul(d, w3);
}
__device__ __forceinline__ void tw3(float2& b, float2& c, float2& d, float2 w) {
    float2 w2 = cmul(w, w), w3 = cmul(w, w2);
    tw3w(b, c, d, w, w2, w3);
}
__device__ __forceinline__ void itw3(float2& b, float2& c, float2& d, float2 w) {
    float2 wc = cconj(w);
    float2 w2 = cmul(wc, wc), w3 = cmul(wc, w2);
    tw3w(b, c, d, wc, w2, w3);
}

// ---------------- transposes ----------------
__global__ __launch_bounds__(256)
void transpose_x_kernel(const float* __restrict__ x) {
    __shared__ float2 tile[32][33];
    const int d0 = blockIdx.x * 32, n0 = blockIdx.y * 32;
    for (int i = threadIdx.y; i < 32; i += 8) {
        const size_t base = (size_t)(n0 + i) * DIMD + d0 + threadIdx.x;
        tile[i][threadIdx.x] = make_float2(x[base], x[base + (size_t)DIML * DIMD]);
    }
    __syncthreads();
    for (int i = threadIdx.y; i < 32; i += 8)
        g_xt[(size_t)(d0 + i) * DIML + n0 + threadIdx.x] = tile[threadIdx.x][i];
}

__global__ __launch_bounds__(256)
void transpose_h_kernel(const float* __restrict__ h) {
    __shared__ float tile[32][33];
    const int d0 = blockIdx.x * 32, n0 = blockIdx.y * 32;
    for (int i = threadIdx.y; i < 32; i += 8)
        tile[i][threadIdx.x] = h[(size_t)(n0 + i) * DIMD + d0 + threadIdx.x];
    __syncthreads();
    for (int i = threadIdx.y; i < 32; i += 8)
        g_ht[(size_t)(d0 + i) * DIML + n0 + threadIdx.x] = tile[threadIdx.x][i];
}

__global__ __launch_bounds__(256)
void transpose_out_kernel(const float* __restrict__ bias, float* __restrict__ y) {
    __shared__ float2 tile[32][33];
    const int n0 = blockIdx.x * 32, d0 = blockIdx.y * 32;
    for (int i = threadIdx.y; i < 32; i += 8)
        tile[i][threadIdx.x] = g_ys[(size_t)(d0 + i) * DIML + n0 + threadIdx.x];
    __syncthreads();
    for (int i = threadIdx.y; i < 32; i += 8) {
        const int d = d0 + threadIdx.x;
        const int n = n0 + i;
        const float bv = __ldg(&bias[d]);
        const float2 v = tile[threadIdx.x][i];
        y[(size_t)n * DIMD + d]          = v.x + bv;
        y[(size_t)(DIML + n) * DIMD + d] = v.y + bv;
    }
}

// ================= pass helpers =============================================

// Pass A: stages m=4096, m=1024 on v[a][b] (element t + 1024b + 4096a), t<1024
__device__ __forceinline__ void passA_fwd(float2 v[4][4], const float2* sA1024,
                                          const float2* sT4, int t) {
    const float2 at = sA1024[t];
    #pragma unroll
    for (int b = 0; b < 4; b++) {
        bfly(v[0][b], v[1][b], v[2][b], v[3][b]);
        float2 w = (b == 0) ? at : cmul(at, sT4[b]);   // W^{t+1024b}
        tw3(v[1][b], v[2][b], v[3][b], w);
    }
    float2 w1 = cmul(at, at); w1 = cmul(w1, w1);       // OT1024[t] = at^4
    float2 w2 = cmul(w1, w1), w3 = cmul(w1, w2);
    #pragma unroll
    for (int a = 0; a < 4; a++) {
        bfly(v[a][0], v[a][1], v[a][2], v[a][3]);
        tw3w(v[a][1], v[a][2], v[a][3], w1, w2, w3);
    }
}

// Pass B dual-group: stages m=256, m=64 for t = tid and tid+512.
// Both groups share rp -> identical twiddles; loads for both issued up front.
__device__ __forceinline__ void passB_fwd2(float2* sA, const float2* sW1024,
                                           const float2* sB256, int tid) {
    const int u = tid >> 6, rp = tid & 63;
    const int base0 = u * 1024 + rp;
    const int base1 = base0 + 8192;       // (u+8)*1024 + rp
    float2 v0[4][4], v1[4][4];
    #pragma unroll
    for (int a = 0; a < 4; a++)
        #pragma unroll
        for (int b = 0; b < 4; b++) {
            v0[a][b] = sA[SWZ(base0 + 64 * b + 256 * a)];
            v1[a][b] = sA[SWZ(base1 + 64 * b + 256 * a)];
        }
    float2 tb[4];
    #pragma unroll
    for (int b = 0; b < 4; b++) tb[b] = sW1024[rp + 64 * b];
    float2 w1 = sB256[rp];
    float2 w2 = cmul(w1, w1), w3 = cmul(w1, w2);
    #pragma unroll
    for (int b = 0; b < 4; b++) {
        bfly(v0[0][b], v0[1][b], v0[2][b], v0[3][b]);
        tw3(v0[1][b], v0[2][b], v0[3][b], tb[b]);
        bfly(v1[0][b], v1[1][b], v1[2][b], v1[3][b]);
        tw3(v1[1][b], v1[2][b], v1[3][b], tb[b]);
    }
    #pragma unroll
    for (int a = 0; a < 4; a++) {
        bfly(v0[a][0], v0[a][1], v0[a][2], v0[a][3]);
        tw3w(v0[a][1], v0[a][2], v0[a][3], w1, w2, w3);
        bfly(v1[a][0], v1[a][1], v1[a][2], v1[a][3]);
        tw3w(v1[a][1], v1[a][2], v1[a][3], w1, w2, w3);
    }
    #pragma unroll
    for (int a = 0; a < 4; a++)
        #pragma unroll
        for (int b = 0; b < 4; b++) {
            sA[SWZ(base0 + 64 * b + 256 * a)] = v0[a][b];
            sA[SWZ(base1 + 64 * b + 256 * a)] = v1[a][b];
        }
}

__device__ __forceinline__ void passB_inv2(float2* sA, const float2* sW1024,
                                           const float2* sB256, int tid) {
    const int u = tid >> 6, rp = tid & 63;
    const int base0 = u * 1024 + rp;
    const int base1 = base0 + 8192;
    float2 v0[4][4], v1[4][4];
    #pragma unroll
    for (int a = 0; a < 4; a++)
        #pragma unroll
        for (int b = 0; b < 4; b++) {
            v0[a][b] = sA[SWZ(base0 + 64 * b + 256 * a)];
            v1[a][b] = sA[SWZ(base1 + 64 * b + 256 * a)];
        }
    float2 w1 = cconj(sB256[rp]);
    float2 w2 = cmul(w1, w1), w3 = cmul(w1, w2);
    float2 tb[4];
    #pragma unroll
    for (int b = 0; b < 4; b++) tb[b] = sW1024[rp + 64 * b];
    #pragma unroll
    for (int a = 0; a < 4; a++) {
        tw3w(v0[a][1], v0[a][2], v0[a][3], w1, w2, w3);
        ibfly(v0[a][0], v0[a][1], v0[a][2], v0[a][3]);
        tw3w(v1[a][1], v1[a][2], v1[a][3], w1, w2, w3);
        ibfly(v1[a][0], v1[a][1], v1[a][2], v1[a][3]);
    }
    #pragma unroll
    for (int b = 0; b < 4; b++) {
        itw3(v0[1][b], v0[2][b], v0[3][b], tb[b]);
        ibfly(v0[0][b], v0[1][b], v0[2][b], v0[3][b]);
        itw3(v1[1][b], v1[2][b], v1[3][b], tb[b]);
        ibfly(v1[0][b], v1[1][b], v1[2][b], v1[3][b]);
    }
    #pragma unroll
    for (int a = 0; a < 4; a++)
        #pragma unroll
        for (int b = 0; b < 4; b++) {
            sA[SWZ(base0 + 64 * b + 256 * a)] = v0[a][b];
            sA[SWZ(base1 + 64 * b + 256 * a)] = v1[a][b];
        }
}

// Pass C dual-group: stage m=16 for t = tid and tid+512 (shared rq twiddles).
__device__ __forceinline__ void passC_fwd2(float2* sA, const float2* sT16, int tid) {
    const int rq = tid & 15, qb = tid >> 4;
    const int base0 = qb * 64 + rq;
    const int base1 = base0 + 2048;       // (qb+32)*64 + rq
    float2 v0[4][4], v1[4][4];
    #pragma unroll
    for (int s = 0; s < 4; s++)
        #pragma unroll
        for (int a = 0; a < 4; a++) {
            v0[s][a] = sA[SWZ(base0 + 4096 * s + 16 * a)];
            v1[s][a] = sA[SWZ(base1 + 4096 * s + 16 * a)];
        }
    float2 w1 = sT16[rq];
    float2 w2 = cmul(w1, w1), w3 = cmul(w1, w2);
    #pragma unroll
    for (int s = 0; s < 4; s++) {
        bfly(v0[s][0], v0[s][1], v0[s][2], v0[s][3]);
        tw3w(v0[s][1], v0[s][2], v0[s][3], w1, w2, w3);
        bfly(v1[s][0], v1[s][1], v1[s][2], v1[s][3]);
        tw3w(v1[s][1], v1[s][2], v1[s][3], w1, w2, w3);
    }
    #pragma unroll
    for (int s = 0; s < 4; s++)
        #pragma unroll
        for (int a = 0; a < 4; a++) {
            sA[SWZ(base0 + 4096 * s + 16 * a)] = v0[s][a];
            sA[SWZ(base1 + 4096 * s + 16 * a)] = v1[s][a];
        }
}

__device__ __forceinline__ void passC_inv2(float2* sA, const float2* sT16, int tid) {
    const int rq = tid & 15, qb = tid >> 4;
    const int base0 = qb * 64 + rq;
    const int base1 = base0 + 2048;
    float2 v0[4][4], v1[4][4];
    #pragma unroll
    for (int s = 0; s < 4; s++)
        #pragma unroll
        for (int a = 0; a < 4; a++) {
            v0[s][a] = sA[SWZ(base0 + 4096 * s + 16 * a)];
            v1[s][a] = sA[SWZ(base1 + 4096 * s + 16 * a)];
        }
    float2 w1 = cconj(sT16[rq]);
    float2 w2 = cmul(w1, w1), w3 = cmul(w1, w2);
    #pragma unroll
    for (int s = 0; s < 4; s++) {
        tw3w(v0[s][1], v0[s][2], v0[s][3], w1, w2, w3);
        ibfly(v0[s][0], v0[s][1], v0[s][2], v0[s][3]);
        tw3w(v1[s][1], v1[s][2], v1[s][3], w1, w2, w3);
        ibfly(v1[s][0], v1[s][1], v1[s][2], v1[s][3]);
    }
    #pragma unroll
    for (int s = 0; s < 4; s++)
        #pragma unroll
        for (int a = 0; a < 4; a++) {
            sA[SWZ(base0 + 4096 * s + 16 * a)] = v0[s][a];
            sA[SWZ(base1 + 4096 * s + 16 * a)] = v1[s][a];
        }
}

// Pass D forward: stages m=4, m=1 on u16 (elements 16t..16t+15)
__device__ __forceinline__ void passD_fwd(float2 u16[16], const float2* sT4) {
    #pragma unroll
    for (int r = 0; r < 4; r++) {
        bfly(u16[r], u16[r + 4], u16[r + 8], u16[r + 12]);
        tw3(u16[r + 4], u16[r + 8], u16[r + 12], sT4[r]);
    }
    #pragma unroll
    for (int g = 0; g < 4; g++)
        bfly(u16[4 * g], u16[4 * g + 1], u16[4 * g + 2], u16[4 * g + 3]);
}

// ================= fused conv: h-FFT (H -> smem fp16) + x-FFT + inv =========
__global__ __launch_bounds__(NT, 1)
void fft_conv_fused_kernel() {
    extern __shared__ char smem[];
    float2* sA     = (float2*)(smem);
    __half2* sH    = (__half2*)(smem + 131072);
    float2* sA1024 = (float2*)(smem + 196608);
    float2* sB256  = (float2*)(smem + 204800);
    float2* sW1024 = (float2*)(smem + 206848);
    float2* sT16   = (float2*)(smem + 208896);
    float2* sT4    = (float2*)(smem + 209024);

    const int tid = threadIdx.x, d = blockIdx.x;

    // ---- table init ----
    for (int j = tid; j < 1024; j += NT) {
        float s, c;
        sincospif((float)j / 8192.0f, &s, &c);       // W^j
        sA1024[j] = make_float2(c, -s);
    }
    if (tid < 256) {
        float s, c;
        sincospif((float)tid / 128.0f, &s, &c);      // W_256^j
        sB256[tid] = make_float2(c, -s);
        sincospif((float)tid / 512.0f, &s, &c);      // W_1024^j
        sW1024[tid] = make_float2(c, -s);
    }
    if (tid < 16) {
        float s, c;
        sincospif((float)tid / 32.0f, &s, &c);       // W_64^j
        sT16[tid] = make_float2(c, -s);
    }
    if (tid < 4) {
        float s, c;
        sincospif((float)tid / 8.0f, &s, &c);        // W_16^j == W^{1024j}
        sT4[tid] = make_float2(c, -s);
    }
    __syncthreads();

    // ================= h forward FFT -> sH (fp16) =================
    {
        const float* hp = g_ht + (size_t)d * DIML;
        #pragma unroll
        for (int g = 0; g < 2; g++) {
            const int t = tid + 512 * g;
            float2 v[4][4];
            #pragma unroll
            for (int a = 0; a < 4; a++)
                #pragma unroll
                for (int b = 0; b < 4; b++)
                    v[a][b] = (a < 2) ? make_float2(hp[t + 1024 * b + 4096 * a], 0.0f)
                                      : make_float2(0.0f, 0.0f);
            passA_fwd(v, sA1024, sT4, t);
            #pragma unroll
            for (int a = 0; a < 4; a++)
                #pragma unroll
                for (int b = 0; b < 4; b++)
                    sA[SWZ(t + 1024 * b + 4096 * a)] = v[a][b];
        }
        __syncthreads();
        passB_fwd2(sA, sW1024, sB256, tid);
        __syncthreads();
        passC_fwd2(sA, sT16, tid);
        __syncthreads();
        #pragma unroll
        for (int g = 0; g < 2; g++) {
            const int t = tid + 512 * g;
            float2 u16[16];
            #pragma unroll
            for (int j = 0; j < 16; j++) u16[j] = sA[SWZ(16 * t + j)];
            passD_fwd(u16, sT4);
            #pragma unroll
            for (int j = 0; j < 16; j++)
                sH[j * 1024 + t] = __floats2half2_rn(u16[j].x, u16[j].y);
        }
    }
    __syncthreads();              // all pass-D reads of sA done before x reuses it

    // ================= x forward FFT, * H, inverse FFT =================
    {
        const float2* xp = g_xt + (size_t)d * DIML;
        #pragma unroll
        for (int g = 0; g < 2; g++) {
            const int t = tid + 512 * g;
            float2 v[4][4];
            #pragma unroll
            for (int a = 0; a < 4; a++)
                #pragma unroll
                for (int b = 0; b < 4; b++)
                    v[a][b] = (a < 2) ? xp[t + 1024 * b + 4096 * a] : make_float2(0.0f, 0.0f);
            passA_fwd(v, sA1024, sT4, t);
            #pragma unroll
            for (int a = 0; a < 4; a++)
                #pragma unroll
                for (int b = 0; b < 4; b++)
                    sA[SWZ(t + 1024 * b + 4096 * a)] = v[a][b];
        }
        __syncthreads();
        passB_fwd2(sA, sW1024, sB256, tid);
        __syncthreads();
        passC_fwd2(sA, sT16, tid);
        __syncthreads();

        // pass D: fwd(4,1) + H multiply + inv(1,4)
        #pragma unroll
        for (int g = 0; g < 2; g++) {
            const int t = tid + 512 * g;
            float2 u16[16];
            #pragma unroll
            for (int j = 0; j < 16; j++) u16[j] = sA[SWZ(16 * t + j)];
            passD_fwd(u16, sT4);

            #pragma unroll
            for (int j = 0; j < 16; j++) {
                float2 hv = __half22float2(sH[j * 1024 + t]);
                u16[j] = cmul(u16[j], hv);
            }

            #pragma unroll
            for (int q = 0; q < 4; q++)
                ibfly(u16[4 * q], u16[4 * q + 1], u16[4 * q + 2], u16[4 * q + 3]);
            #pragma unroll
            for (int r = 0; r < 4; r++) {
                itw3(u16[r + 4], u16[r + 8], u16[r + 12], sT4[r]);
                ibfly(u16[r], u16[r + 4], u16[r + 8], u16[r + 12]);
            }
            #pragma unroll
            for (int j = 0; j < 16; j++) sA[SWZ(16 * t + j)] = u16[j];
        }
        __syncthreads();

        passC_inv2(sA, sT16, tid);
        __syncthreads();
        passB_inv2(sA, sW1024, sB256, tid);
        __syncthreads();

        // pass A': inverse stages 1024 then 4096, scale + store
        const float scale = 1.0f / (float)NFFT;
        float2* yp = g_ys + (size_t)d * DIML;
        #pragma unroll
        for (int g = 0; g < 2; g++) {
            const int t = tid + 512 * g;
            float2 v[4][4];
            #pragma unroll
            for (int a = 0; a < 4; a++)
                #pragma unroll
                for (int b = 0; b < 4; b++)
                    v[a][b] = sA[SWZ(t + 1024 * b + 4096 * a)];
            const float2 at = sA1024[t];
            float2 w1 = cmul(at, at); w1 = cmul(w1, w1);   // at^4
            w1 = cconj(w1);
            float2 w2 = cmul(w1, w1), w3 = cmul(w1, w2);
            #pragma unroll
            for (int a = 0; a < 4; a++) {
                tw3w(v[a][1], v[a][2], v[a][3], w1, w2, w3);
                ibfly(v[a][0], v[a][1], v[a][2], v[a][3]);
            }
            #pragma unroll
            for (int b = 0; b < 4; b++) {
                float2 w = (b == 0) ? at : cmul(at, sT4[b]);
                itw3(v[1][b], v[2][b], v[3][b], w);
                ibfly(v[0][b], v[1][b], v[2][b], v[3][b]);
            }
            #pragma unroll
            for (int a = 0; a < 2; a++)
                #pragma unroll
                for (int b = 0; b < 4; b++) {
                    float2 r = v[a][b];
                    yp[t + 1024 * b + 4096 * a] = make_float2(r.x * scale, r.y * scale);
                }
        }
    }
}

// ---------------------------------------------------------------------------
extern "C" void kernel_launch(void* const* d_in, const int* in_sizes, int n_in,
                              void* d_out, int out_size) {
    const float* x    = (const float*)d_in[0];
    const float* h    = (const float*)d_in[1];
    const float* bias = (const float*)d_in[2];
    float* y = (float*)d_out;

    cudaFuncSetAttribute(fft_conv_fused_kernel,
                         cudaFuncAttributeMaxDynamicSharedMemorySize, SMEM_BYTES);

    transpose_x_kernel<<<dim3(DIMD / 32, DIML / 32), dim3(32, 8)>>>(x);
    transpose_h_kernel<<<dim3(DIMD / 32, DIML / 32), dim3(32, 8)>>>(h);
    fft_conv_fused_kernel<<<DIMD, NT, SMEM_BYTES>>>();
    transpose_out_kernel<<<dim3(DIML / 32, DIMD / 32), dim3(32, 8)>>>(bias, y);
}

// round 11
// speedup vs baseline: 1.0651x; 1.0651x over previous
#include <cuda_runtime.h>
#include <cuda_fp16.h>
#include <cstdint>

#define NFFT 16384
#define DIML 8192
#define DIMD 1024
#define NT   512        // 512 threads, 2 groups of 16 elements per thread

// conflict-killing swizzle for sA: XOR low 4 bits with bits[7:4] (self-inverse)
#define SWZ(i) ((i) ^ (((i) >> 4) & 15))

// smem layout (bytes)
//   sA     : float2[16384]   @ 0        (131072)
//   sH     : half2 [16384]   @ 131072   (65536)
//   sA1024 : float2[1024]    @ 196608   (8192)   W^j,      j<1024 (W = W_16384)
//   sB256  : float2[256]     @ 204800   (2048)   W_256^j,  j<256   (stage-64 tw)
//   sW1024 : float2[256]     @ 206848   (2048)   W_1024^j, j<256   (stage-256 tw)
//   sT16   : float2[16]      @ 208896   (128)    W_64^j            (stage-16 tw)
//   sT4    : float2[4]       @ 209024   (32)     W_16^j == W^{1024j} (stage-4 + K4)
#define SMEM_BYTES 209056

// ---------------- device scratch ----------------
__device__ float2 g_xt[(size_t)DIMD * DIML];       // transposed x, batches packed
__device__ float  g_ht[(size_t)DIMD * DIML];       // transposed h
__device__ float2 g_ys[(size_t)DIMD * DIML];       // transposed scaled output

__device__ __forceinline__ float2 cmul(float2 a, float2 b) {
    return make_float2(a.x * b.x - a.y * b.y, a.x * b.y + a.y * b.x);
}
__device__ __forceinline__ float2 cconj(float2 a) { return make_float2(a.x, -a.y); }
__device__ __forceinline__ float2 cadd(float2 a, float2 b) { return make_float2(a.x + b.x, a.y + b.y); }
__device__ __forceinline__ float2 csub(float2 a, float2 b) { return make_float2(a.x - b.x, a.y - b.y); }

// DIF forward radix-4 butterfly (in place)
__device__ __forceinline__ void bfly(float2& a, float2& b, float2& c, float2& d) {
    float2 t0 = cadd(a, c), t1 = csub(a, c), t2 = cadd(b, d), t3 = csub(b, d);
    float2 t3s = make_float2(t3.y, -t3.x);     // -i * t3
    a = cadd(t0, t2);
    c = csub(t0, t2);
    b = cadd(t1, t3s);
    d = csub(t1, t3s);
}
// inverse radix-4 butterfly (unnormalized)
__device__ __forceinline__ void ibfly(float2& a, float2& b, float2& c, float2& d) {
    float2 u0 = cadd(a, c), u1 = csub(a, c), u2 = cadd(b, d), u3 = csub(b, d);
    float2 u3s = make_float2(u3.y, -u3.x);
    a = cadd(u0, u2);
    c = csub(u0, u2);
    b = csub(u1, u3s);
    d = cadd(u1, u3s);
}
__device__ __forceinline__ void tw3w(float2& b, float2& c, float2& d,
                                     float2 w1, float2 w2, float2 w3) {
    b = cmul(b, w1); c = cmul(c, w2); d = cmul(d, w3);
}
__device__ __forceinline__ void tw3(float2& b, float2& c, float2& d, float2 w) {
    float2 w2 = cmul(w, w), w3 = cmul(w, w2);
    tw3w(b, c, d, w, w2, w3);
}
__device__ __forceinline__ void itw3(float2& b, float2& c, float2& d, float2 w) {
    float2 wc = cconj(w);
    float2 w2 = cmul(wc, wc), w3 = cmul(wc, w2);
    tw3w(b, c, d, wc, w2, w3);
}

// ---------------- transposes ----------------
// merged x/h input transpose: blockIdx.z = 0 -> x tile, 1 -> h tile
__global__ __launch_bounds__(256)
void transpose_in_kernel(const float* __restrict__ x, const float* __restrict__ h) {
    const int d0 = blockIdx.x * 32, n0 = blockIdx.y * 32;
    if (blockIdx.z == 0) {
        __shared__ float2 tile[32][33];
        for (int i = threadIdx.y; i < 32; i += 8) {
            const size_t base = (size_t)(n0 + i) * DIMD + d0 + threadIdx.x;
            tile[i][threadIdx.x] = make_float2(x[base], x[base + (size_t)DIML * DIMD]);
        }
        __syncthreads();
        for (int i = threadIdx.y; i < 32; i += 8)
            g_xt[(size_t)(d0 + i) * DIML + n0 + threadIdx.x] = tile[threadIdx.x][i];
    } else {
        __shared__ float tileh[32][33];
        for (int i = threadIdx.y; i < 32; i += 8)
            tileh[i][threadIdx.x] = h[(size_t)(n0 + i) * DIMD + d0 + threadIdx.x];
        __syncthreads();
        for (int i = threadIdx.y; i < 32; i += 8)
            g_ht[(size_t)(d0 + i) * DIML + n0 + threadIdx.x] = tileh[threadIdx.x][i];
    }
}

__global__ __launch_bounds__(256)
void transpose_out_kernel(const float* __restrict__ bias, float* __restrict__ y) {
    __shared__ float2 tile[32][33];
    const int n0 = blockIdx.x * 32, d0 = blockIdx.y * 32;
    for (int i = threadIdx.y; i < 32; i += 8)
        tile[i][threadIdx.x] = g_ys[(size_t)(d0 + i) * DIML + n0 + threadIdx.x];
    __syncthreads();
    for (int i = threadIdx.y; i < 32; i += 8) {
        const int d = d0 + threadIdx.x;
        const int n = n0 + i;
        const float bv = __ldg(&bias[d]);
        const float2 v = tile[threadIdx.x][i];
        y[(size_t)n * DIMD + d]          = v.x + bv;
        y[(size_t)(DIML + n) * DIMD + d] = v.y + bv;
    }
}

// ================= pass helpers =============================================

// Pass A: stages m=4096, m=1024 on v[a][b] (element t + 1024b + 4096a), t<1024
__device__ __forceinline__ void passA_fwd(float2 v[4][4], const float2* sA1024,
                                          const float2* sT4, int t) {
    const float2 at = sA1024[t];
    #pragma unroll
    for (int b = 0; b < 4; b++) {
        bfly(v[0][b], v[1][b], v[2][b], v[3][b]);
        float2 w = (b == 0) ? at : cmul(at, sT4[b]);   // W^{t+1024b}
        tw3(v[1][b], v[2][b], v[3][b], w);
    }
    float2 w1 = cmul(at, at); w1 = cmul(w1, w1);       // OT1024[t] = at^4
    float2 w2 = cmul(w1, w1), w3 = cmul(w1, w2);
    #pragma unroll
    for (int a = 0; a < 4; a++) {
        bfly(v[a][0], v[a][1], v[a][2], v[a][3]);
        tw3w(v[a][1], v[a][2], v[a][3], w1, w2, w3);
    }
}

// Pass B: stages m=256, m=64. element e(a,b) = u*1024 + rp + 64b + 256a
__device__ __forceinline__ void passB_fwd(float2* sA, const float2* sW1024,
                                          const float2* sB256, int t) {
    const int u = t >> 6, rp = t & 63;
    const int base = u * 1024 + rp;
    float2 v[4][4];
    #pragma unroll
    for (int a = 0; a < 4; a++)
        #pragma unroll
        for (int b = 0; b < 4; b++)
            v[a][b] = sA[SWZ(base + 64 * b + 256 * a)];
    #pragma unroll
    for (int b = 0; b < 4; b++) {
        bfly(v[0][b], v[1][b], v[2][b], v[3][b]);
        tw3(v[1][b], v[2][b], v[3][b], sW1024[rp + 64 * b]);
    }
    float2 w1 = sB256[rp];
    float2 w2 = cmul(w1, w1), w3 = cmul(w1, w2);
    #pragma unroll
    for (int a = 0; a < 4; a++) {
        bfly(v[a][0], v[a][1], v[a][2], v[a][3]);
        tw3w(v[a][1], v[a][2], v[a][3], w1, w2, w3);
    }
    #pragma unroll
    for (int a = 0; a < 4; a++)
        #pragma unroll
        for (int b = 0; b < 4; b++)
            sA[SWZ(base + 64 * b + 256 * a)] = v[a][b];
}

// Pass C: stage m=16. element e(s,a) = qb*64 + rq + 4096s + 16a
__device__ __forceinline__ void passC_fwd(float2* sA, const float2* sT16, int t) {
    const int rq = t & 15, qb = t >> 4;
    const int base = qb * 64 + rq;
    float2 v[4][4];
    #pragma unroll
    for (int s = 0; s < 4; s++)
        #pragma unroll
        for (int a = 0; a < 4; a++)
            v[s][a] = sA[SWZ(base + 4096 * s + 16 * a)];
    float2 w1 = sT16[rq];
    float2 w2 = cmul(w1, w1), w3 = cmul(w1, w2);
    #pragma unroll
    for (int s = 0; s < 4; s++) {
        bfly(v[s][0], v[s][1], v[s][2], v[s][3]);
        tw3w(v[s][1], v[s][2], v[s][3], w1, w2, w3);
    }
    #pragma unroll
    for (int s = 0; s < 4; s++)
        #pragma unroll
        for (int a = 0; a < 4; a++)
            sA[SWZ(base + 4096 * s + 16 * a)] = v[s][a];
}

// Pass D forward: stages m=4, m=1 on u16 (elements 16t..16t+15)
__device__ __forceinline__ void passD_fwd(float2 u16[16], const float2* sT4) {
    #pragma unroll
    for (int r = 0; r < 4; r++) {
        bfly(u16[r], u16[r + 4], u16[r + 8], u16[r + 12]);
        tw3(u16[r + 4], u16[r + 8], u16[r + 12], sT4[r]);
    }
    #pragma unroll
    for (int g = 0; g < 4; g++)
        bfly(u16[4 * g], u16[4 * g + 1], u16[4 * g + 2], u16[4 * g + 3]);
}

// inverse pass C'
__device__ __forceinline__ void passC_inv(float2* sA, const float2* sT16, int t) {
    const int rq = t & 15, qb = t >> 4;
    const int base = qb * 64 + rq;
    float2 w1 = cconj(sT16[rq]);
    float2 w2 = cmul(w1, w1), w3 = cmul(w1, w2);
    float2 v[4][4];
    #pragma unroll
    for (int s = 0; s < 4; s++)
        #pragma unroll
        for (int a = 0; a < 4; a++)
            v[s][a] = sA[SWZ(base + 4096 * s + 16 * a)];
    #pragma unroll
    for (int s = 0; s < 4; s++) {
        tw3w(v[s][1], v[s][2], v[s][3], w1, w2, w3);
        ibfly(v[s][0], v[s][1], v[s][2], v[s][3]);
    }
    #pragma unroll
    for (int s = 0; s < 4; s++)
        #pragma unroll
        for (int a = 0; a < 4; a++)
            sA[SWZ(base + 4096 * s + 16 * a)] = v[s][a];
}

// inverse pass B'
__device__ __forceinline__ void passB_inv(float2* sA, const float2* sW1024,
                                          const float2* sB256, int t) {
    const int u = t >> 6, rp = t & 63;
    const int base = u * 1024 + rp;
    float2 v[4][4];
    #pragma unroll
    for (int a = 0; a < 4; a++)
        #pragma unroll
        for (int b = 0; b < 4; b++)
            v[a][b] = sA[SWZ(base + 64 * b + 256 * a)];
    float2 w1 = cconj(sB256[rp]);
    float2 w2 = cmul(w1, w1), w3 = cmul(w1, w2);
    #pragma unroll
    for (int a = 0; a < 4; a++) {
        tw3w(v[a][1], v[a][2], v[a][3], w1, w2, w3);
        ibfly(v[a][0], v[a][1], v[a][2], v[a][3]);
    }
    #pragma unroll
    for (int b = 0; b < 4; b++) {
        itw3(v[1][b], v[2][b], v[3][b], sW1024[rp + 64 * b]);
        ibfly(v[0][b], v[1][b], v[2][b], v[3][b]);
    }
    #pragma unroll
    for (int a = 0; a < 4; a++)
        #pragma unroll
        for (int b = 0; b < 4; b++)
            sA[SWZ(base + 64 * b + 256 * a)] = v[a][b];
}

// ================= fused conv: h-FFT (H -> smem fp16) + x-FFT + inv =========
__global__ __launch_bounds__(NT, 1)
void fft_conv_fused_kernel() {
    extern __shared__ char smem[];
    float2* sA     = (float2*)(smem);
    __half2* sH    = (__half2*)(smem + 131072);
    float2* sA1024 = (float2*)(smem + 196608);
    float2* sB256  = (float2*)(smem + 204800);
    float2* sW1024 = (float2*)(smem + 206848);
    float2* sT16   = (float2*)(smem + 208896);
    float2* sT4    = (float2*)(smem + 209024);

    const int tid = threadIdx.x, d = blockIdx.x;

    // ---- table init ----
    for (int j = tid; j < 1024; j += NT) {
        float s, c;
        sincospif((float)j / 8192.0f, &s, &c);       // W^j
        sA1024[j] = make_float2(c, -s);
    }
    if (tid < 256) {
        float s, c;
        sincospif((float)tid / 128.0f, &s, &c);      // W_256^j
        sB256[tid] = make_float2(c, -s);
        sincospif((float)tid / 512.0f, &s, &c);      // W_1024^j
        sW1024[tid] = make_float2(c, -s);
    }
    if (tid < 16) {
        float s, c;
        sincospif((float)tid / 32.0f, &s, &c);       // W_64^j
        sT16[tid] = make_float2(c, -s);
    }
    if (tid < 4) {
        float s, c;
        sincospif((float)tid / 8.0f, &s, &c);        // W_16^j == W^{1024j}
        sT4[tid] = make_float2(c, -s);
    }
    __syncthreads();

    // ================= h forward FFT -> sH (fp16) =================
    {
        const float* hp = g_ht + (size_t)d * DIML;
        #pragma unroll
        for (int g = 0; g < 2; g++) {
            const int t = tid + 512 * g;
            float2 v[4][4];
            #pragma unroll
            for (int a = 0; a < 4; a++)
                #pragma unroll
                for (int b = 0; b < 4; b++)
                    v[a][b] = (a < 2) ? make_float2(hp[t + 1024 * b + 4096 * a], 0.0f)
                                      : make_float2(0.0f, 0.0f);
            passA_fwd(v, sA1024, sT4, t);
            #pragma unroll
            for (int a = 0; a < 4; a++)
                #pragma unroll
                for (int b = 0; b < 4; b++)
                    sA[SWZ(t + 1024 * b + 4096 * a)] = v[a][b];
        }
        __syncthreads();
        passB_fwd(sA, sW1024, sB256, tid);
        passB_fwd(sA, sW1024, sB256, tid + 512);
        __syncthreads();
        passC_fwd(sA, sT16, tid);
        passC_fwd(sA, sT16, tid + 512);
        __syncthreads();
        #pragma unroll
        for (int g = 0; g < 2; g++) {
            const int t = tid + 512 * g;
            float2 u16[16];
            #pragma unroll
            for (int j = 0; j < 16; j++) u16[j] = sA[SWZ(16 * t + j)];
            passD_fwd(u16, sT4);
            #pragma unroll
            for (int j = 0; j < 16; j++)
                sH[j * 1024 + t] = __floats2half2_rn(u16[j].x, u16[j].y);
        }
    }
    __syncthreads();              // all pass-D reads of sA done before x reuses it

    // ================= x forward FFT, * H, inverse FFT =================
    {
        const float2* xp = g_xt + (size_t)d * DIML;
        #pragma unroll
        for (int g = 0; g < 2; g++) {
            const int t = tid + 512 * g;
            float2 v[4][4];
            #pragma unroll
            for (int a = 0; a < 4; a++)
                #pragma unroll
                for (int b = 0; b < 4; b++)
                    v[a][b] = (a < 2) ? xp[t + 1024 * b + 4096 * a] : make_float2(0.0f, 0.0f);
            passA_fwd(v, sA1024, sT4, t);
            #pragma unroll
            for (int a = 0; a < 4; a++)
                #pragma unroll
                for (int b = 0; b < 4; b++)
                    sA[SWZ(t + 1024 * b + 4096 * a)] = v[a][b];
        }
        __syncthreads();
        passB_fwd(sA, sW1024, sB256, tid);
        passB_fwd(sA, sW1024, sB256, tid + 512);
        __syncthreads();
        passC_fwd(sA, sT16, tid);
        passC_fwd(sA, sT16, tid + 512);
        __syncthreads();

        // pass D: fwd(4,1) + H multiply + inv(1,4)
        #pragma unroll
        for (int g = 0; g < 2; g++) {
            const int t = tid + 512 * g;
            float2 u16[16];
            #pragma unroll
            for (int j = 0; j < 16; j++) u16[j] = sA[SWZ(16 * t + j)];
            passD_fwd(u16, sT4);

            #pragma unroll
            for (int j = 0; j < 16; j++) {
                float2 hv = __half22float2(sH[j * 1024 + t]);
                u16[j] = cmul(u16[j], hv);
            }

            #pragma unroll
            for (int q = 0; q < 4; q++)
                ibfly(u16[4 * q], u16[4 * q + 1], u16[4 * q + 2], u16[4 * q + 3]);
            #pragma unroll
            for (int r = 0; r < 4; r++) {
                itw3(u16[r + 4], u16[r + 8], u16[r + 12], sT4[r]);
                ibfly(u16[r], u16[r + 4], u16[r + 8], u16[r + 12]);
            }
            #pragma unroll
            for (int j = 0; j < 16; j++) sA[SWZ(16 * t + j)] = u16[j];
        }
        __syncthreads();

        passC_inv(sA, sT16, tid);
        passC_inv(sA, sT16, tid + 512);
        __syncthreads();
        passB_inv(sA, sW1024, sB256, tid);
        passB_inv(sA, sW1024, sB256, tid + 512);
        __syncthreads();

        // pass A': inverse stages 1024 then 4096, scale + store
        const float scale = 1.0f / (float)NFFT;
        float2* yp = g_ys + (size_t)d * DIML;
        #pragma unroll
        for (int g = 0; g < 2; g++) {
            const int t = tid + 512 * g;
            float2 v[4][4];
            #pragma unroll
            for (int a = 0; a < 4; a++)
                #pragma unroll
                for (int b = 0; b < 4; b++)
                    v[a][b] = sA[SWZ(t + 1024 * b + 4096 * a)];
            const float2 at = sA1024[t];
            float2 w1 = cmul(at, at); w1 = cmul(w1, w1);   // at^4
            w1 = cconj(w1);
            float2 w2 = cmul(w1, w1), w3 = cmul(w1, w2);
            #pragma unroll
            for (int a = 0; a < 4; a++) {
                tw3w(v[a][1], v[a][2], v[a][3], w1, w2, w3);
                ibfly(v[a][0], v[a][1], v[a][2], v[a][3]);
            }
            #pragma unroll
            for (int b = 0; b < 4; b++) {
                float2 w = (b == 0) ? at : cmul(at, sT4[b]);
                itw3(v[1][b], v[2][b], v[3][b], w);
                ibfly(v[0][b], v[1][b], v[2][b], v[3][b]);
            }
            #pragma unroll
            for (int a = 0; a < 2; a++)
                #pragma unroll
                for (int b = 0; b < 4; b++) {
                    float2 r = v[a][b];
                    yp[t + 1024 * b + 4096 * a] = make_float2(r.x * scale, r.y * scale);
                }
        }
    }
}

// ---------------------------------------------------------------------------
extern "C" void kernel_launch(void* const* d_in, const int* in_sizes, int n_in,
                              void* d_out, int out_size) {
    const float* x    = (const float*)d_in[0];
    const float* h    = (const float*)d_in[1];
    const float* bias = (const float*)d_in[2];
    float* y = (float*)d_out;

    cudaFuncSetAttribute(fft_conv_fused_kernel,
                         cudaFuncAttributeMaxDynamicSharedMemorySize, SMEM_BYTES);

    transpose_in_kernel<<<dim3(DIMD / 32, DIML / 32, 2), dim3(32, 8)>>>(x, h);
    fft_conv_fused_kernel<<<DIMD, NT, SMEM_BYTES>>>();
    transpose_out_kernel<<<dim3(DIML / 32, DIMD / 32), dim3(32, 8)>>>(bias, y);
}

// round 12
// speedup vs baseline: 1.1044x; 1.0369x over previous
#include <cuda_runtime.h>
#include <cuda_fp16.h>
#include <cstdint>

#define NFFT 16384
#define DIML 8192
#define DIMD 1024
#define NT   512        // 512 threads, 2 groups of 16 elements per thread

// conflict-killing swizzle for sA: XOR low 4 bits with bits[7:4] (self-inverse)
#define SWZ(i) ((i) ^ (((i) >> 4) & 15))

// smem layout (bytes)
//   sA     : float2[16384]   @ 0        (131072)
//   sH     : half2 [16384]   @ 131072   (65536)
//   sA1024 : float2[1024]    @ 196608   (8192)   W^j,      j<1024 (W = W_16384)
//   sB256  : float2[256]     @ 204800   (2048)   W_256^j,  j<256   (stage-64 tw)
//   sW1024 : float2[256]     @ 206848   (2048)   W_1024^j, j<256   (stage-256 tw)
//   sT16   : float2[16]      @ 208896   (128)    W_64^j            (stage-16 tw)
//   sT4    : float2[4]       @ 209024   (32)     W_16^j == W^{1024j} (stage-4 + K4)
#define SMEM_BYTES 209056

// ---------------- device scratch ----------------
__device__ __half2 g_xt[(size_t)DIMD * DIML];      // transposed x, batches packed (fp16)
__device__ __half  g_ht[(size_t)DIMD * DIML];      // transposed h (fp16)
__device__ float2  g_ys[(size_t)DIMD * DIML];      // transposed scaled output (fp32)

__device__ __forceinline__ float2 cmul(float2 a, float2 b) {
    return make_float2(a.x * b.x - a.y * b.y, a.x * b.y + a.y * b.x);
}
__device__ __forceinline__ float2 cconj(float2 a) { return make_float2(a.x, -a.y); }
__device__ __forceinline__ float2 cadd(float2 a, float2 b) { return make_float2(a.x + b.x, a.y + b.y); }
__device__ __forceinline__ float2 csub(float2 a, float2 b) { return make_float2(a.x - b.x, a.y - b.y); }

// DIF forward radix-4 butterfly (in place)
__device__ __forceinline__ void bfly(float2& a, float2& b, float2& c, float2& d) {
    float2 t0 = cadd(a, c), t1 = csub(a, c), t2 = cadd(b, d), t3 = csub(b, d);
    float2 t3s = make_float2(t3.y, -t3.x);     // -i * t3
    a = cadd(t0, t2);
    c = csub(t0, t2);
    b = cadd(t1, t3s);
    d = csub(t1, t3s);
}
// inverse radix-4 butterfly (unnormalized)
__device__ __forceinline__ void ibfly(float2& a, float2& b, float2& c, float2& d) {
    float2 u0 = cadd(a, c), u1 = csub(a, c), u2 = cadd(b, d), u3 = csub(b, d);
    float2 u3s = make_float2(u3.y, -u3.x);
    a = cadd(u0, u2);
    c = csub(u0, u2);
    b = csub(u1, u3s);
    d = cadd(u1, u3s);
}
__device__ __forceinline__ void tw3w(float2& b, float2& c, float2& d,
                                     float2 w1, float2 w2, float2 w3) {
    b = cmul(b, w1); c = cmul(c, w2); d = cmul(d, w3);
}
__device__ __forceinline__ void tw3(float2& b, float2& c, float2& d, float2 w) {
    float2 w2 = cmul(w, w), w3 = cmul(w, w2);
    tw3w(b, c, d, w, w2, w3);
}
__device__ __forceinline__ void itw3(float2& b, float2& c, float2& d, float2 w) {
    float2 wc = cconj(w);
    float2 w2 = cmul(wc, wc), w3 = cmul(wc, w2);
    tw3w(b, c, d, wc, w2, w3);
}

// ---------------- transposes ----------------
// merged x/h input transpose: blockIdx.z = 0 -> x tile, 1 -> h tile
__global__ __launch_bounds__(256)
void transpose_in_kernel(const float* __restrict__ x, const float* __restrict__ h) {
    const int d0 = blockIdx.x * 32, n0 = blockIdx.y * 32;
    if (blockIdx.z == 0) {
        __shared__ float2 tile[32][33];
        for (int i = threadIdx.y; i < 32; i += 8) {
            const size_t base = (size_t)(n0 + i) * DIMD + d0 + threadIdx.x;
            tile[i][threadIdx.x] = make_float2(x[base], x[base + (size_t)DIML * DIMD]);
        }
        __syncthreads();
        for (int i = threadIdx.y; i < 32; i += 8) {
            float2 v = tile[threadIdx.x][i];
            g_xt[(size_t)(d0 + i) * DIML + n0 + threadIdx.x] =
                __floats2half2_rn(v.x, v.y);
        }
    } else {
        __shared__ float tileh[32][33];
        for (int i = threadIdx.y; i < 32; i += 8)
            tileh[i][threadIdx.x] = h[(size_t)(n0 + i) * DIMD + d0 + threadIdx.x];
        __syncthreads();
        for (int i = threadIdx.y; i < 32; i += 8)
            g_ht[(size_t)(d0 + i) * DIML + n0 + threadIdx.x] =
                __float2half_rn(tileh[threadIdx.x][i]);
    }
}

__global__ __launch_bounds__(256)
void transpose_out_kernel(const float* __restrict__ bias, float* __restrict__ y) {
    __shared__ float2 tile[32][33];
    const int n0 = blockIdx.x * 32, d0 = blockIdx.y * 32;
    for (int i = threadIdx.y; i < 32; i += 8)
        tile[i][threadIdx.x] = g_ys[(size_t)(d0 + i) * DIML + n0 + threadIdx.x];
    __syncthreads();
    for (int i = threadIdx.y; i < 32; i += 8) {
        const int d = d0 + threadIdx.x;
        const int n = n0 + i;
        const float bv = __ldg(&bias[d]);
        const float2 v = tile[threadIdx.x][i];
        y[(size_t)n * DIMD + d]          = v.x + bv;
        y[(size_t)(DIML + n) * DIMD + d] = v.y + bv;
    }
}

// ================= pass helpers =============================================

// Pass A: stages m=4096, m=1024 on v[a][b] (element t + 1024b + 4096a), t<1024
__device__ __forceinline__ void passA_fwd(float2 v[4][4], const float2* sA1024,
                                          const float2* sT4, int t) {
    const float2 at = sA1024[t];
    #pragma unroll
    for (int b = 0; b < 4; b++) {
        bfly(v[0][b], v[1][b], v[2][b], v[3][b]);
        float2 w = (b == 0) ? at : cmul(at, sT4[b]);   // W^{t+1024b}
        tw3(v[1][b], v[2][b], v[3][b], w);
    }
    float2 w1 = cmul(at, at); w1 = cmul(w1, w1);       // OT1024[t] = at^4
    float2 w2 = cmul(w1, w1), w3 = cmul(w1, w2);
    #pragma unroll
    for (int a = 0; a < 4; a++) {
        bfly(v[a][0], v[a][1], v[a][2], v[a][3]);
        tw3w(v[a][1], v[a][2], v[a][3], w1, w2, w3);
    }
}

// Pass B: stages m=256, m=64. element e(a,b) = u*1024 + rp + 64b + 256a
__device__ __forceinline__ void passB_fwd(float2* sA, const float2* sW1024,
                                          const float2* sB256, int t) {
    const int u = t >> 6, rp = t & 63;
    const int base = u * 1024 + rp;
    float2 v[4][4];
    #pragma unroll
    for (int a = 0; a < 4; a++)
        #pragma unroll
        for (int b = 0; b < 4; b++)
            v[a][b] = sA[SWZ(base + 64 * b + 256 * a)];
    #pragma unroll
    for (int b = 0; b < 4; b++) {
        bfly(v[0][b], v[1][b], v[2][b], v[3][b]);
        tw3(v[1][b], v[2][b], v[3][b], sW1024[rp + 64 * b]);
    }
    float2 w1 = sB256[rp];
    float2 w2 = cmul(w1, w1), w3 = cmul(w1, w2);
    #pragma unroll
    for (int a = 0; a < 4; a++) {
        bfly(v[a][0], v[a][1], v[a][2], v[a][3]);
        tw3w(v[a][1], v[a][2], v[a][3], w1, w2, w3);
    }
    #pragma unroll
    for (int a = 0; a < 4; a++)
        #pragma unroll
        for (int b = 0; b < 4; b++)
            sA[SWZ(base + 64 * b + 256 * a)] = v[a][b];
}

// Pass C: stage m=16. element e(s,a) = qb*64 + rq + 4096s + 16a
__device__ __forceinline__ void passC_fwd(float2* sA, const float2* sT16, int t) {
    const int rq = t & 15, qb = t >> 4;
    const int base = qb * 64 + rq;
    float2 v[4][4];
    #pragma unroll
    for (int s = 0; s < 4; s++)
        #pragma unroll
        for (int a = 0; a < 4; a++)
            v[s][a] = sA[SWZ(base + 4096 * s + 16 * a)];
    float2 w1 = sT16[rq];
    float2 w2 = cmul(w1, w1), w3 = cmul(w1, w2);
    #pragma unroll
    for (int s = 0; s < 4; s++) {
        bfly(v[s][0], v[s][1], v[s][2], v[s][3]);
        tw3w(v[s][1], v[s][2], v[s][3], w1, w2, w3);
    }
    #pragma unroll
    for (int s = 0; s < 4; s++)
        #pragma unroll
        for (int a = 0; a < 4; a++)
            sA[SWZ(base + 4096 * s + 16 * a)] = v[s][a];
}

// Pass D forward: stages m=4, m=1 on u16 (elements 16t..16t+15)
__device__ __forceinline__ void passD_fwd(float2 u16[16], const float2* sT4) {
    #pragma unroll
    for (int r = 0; r < 4; r++) {
        bfly(u16[r], u16[r + 4], u16[r + 8], u16[r + 12]);
        tw3(u16[r + 4], u16[r + 8], u16[r + 12], sT4[r]);
    }
    #pragma unroll
    for (int g = 0; g < 4; g++)
        bfly(u16[4 * g], u16[4 * g + 1], u16[4 * g + 2], u16[4 * g + 3]);
}

// inverse pass C'
__device__ __forceinline__ void passC_inv(float2* sA, const float2* sT16, int t) {
    const int rq = t & 15, qb = t >> 4;
    const int base = qb * 64 + rq;
    float2 w1 = cconj(sT16[rq]);
    float2 w2 = cmul(w1, w1), w3 = cmul(w1, w2);
    float2 v[4][4];
    #pragma unroll
    for (int s = 0; s < 4; s++)
        #pragma unroll
        for (int a = 0; a < 4; a++)
            v[s][a] = sA[SWZ(base + 4096 * s + 16 * a)];
    #pragma unroll
    for (int s = 0; s < 4; s++) {
        tw3w(v[s][1], v[s][2], v[s][3], w1, w2, w3);
        ibfly(v[s][0], v[s][1], v[s][2], v[s][3]);
    }
    #pragma unroll
    for (int s = 0; s < 4; s++)
        #pragma unroll
        for (int a = 0; a < 4; a++)
            sA[SWZ(base + 4096 * s + 16 * a)] = v[s][a];
}

// inverse pass B'
__device__ __forceinline__ void passB_inv(float2* sA, const float2* sW1024,
                                          const float2* sB256, int t) {
    const int u = t >> 6, rp = t & 63;
    const int base = u * 1024 + rp;
    float2 v[4][4];
    #pragma unroll
    for (int a = 0; a < 4; a++)
        #pragma unroll
        for (int b = 0; b < 4; b++)
            v[a][b] = sA[SWZ(base + 64 * b + 256 * a)];
    float2 w1 = cconj(sB256[rp]);
    float2 w2 = cmul(w1, w1), w3 = cmul(w1, w2);
    #pragma unroll
    for (int a = 0; a < 4; a++) {
        tw3w(v[a][1], v[a][2], v[a][3], w1, w2, w3);
        ibfly(v[a][0], v[a][1], v[a][2], v[a][3]);
    }
    #pragma unroll
    for (int b = 0; b < 4; b++) {
        itw3(v[1][b], v[2][b], v[3][b], sW1024[rp + 64 * b]);
        ibfly(v[0][b], v[1][b], v[2][b], v[3][b]);
    }
    #pragma unroll
    for (int a = 0; a < 4; a++)
        #pragma unroll
        for (int b = 0; b < 4; b++)
            sA[SWZ(base + 64 * b + 256 * a)] = v[a][b];
}

// ================= fused conv: h-FFT (H -> smem fp16) + x-FFT + inv =========
__global__ __launch_bounds__(NT, 1)
void fft_conv_fused_kernel() {
    extern __shared__ char smem[];
    float2* sA     = (float2*)(smem);
    __half2* sH    = (__half2*)(smem + 131072);
    float2* sA1024 = (float2*)(smem + 196608);
    float2* sB256  = (float2*)(smem + 204800);
    float2* sW1024 = (float2*)(smem + 206848);
    float2* sT16   = (float2*)(smem + 208896);
    float2* sT4    = (float2*)(smem + 209024);

    const int tid = threadIdx.x, d = blockIdx.x;

    // ---- table init ----
    for (int j = tid; j < 1024; j += NT) {
        float s, c;
        sincospif((float)j / 8192.0f, &s, &c);       // W^j
        sA1024[j] = make_float2(c, -s);
    }
    if (tid < 256) {
        float s, c;
        sincospif((float)tid / 128.0f, &s, &c);      // W_256^j
        sB256[tid] = make_float2(c, -s);
        sincospif((float)tid / 512.0f, &s, &c);      // W_1024^j
        sW1024[tid] = make_float2(c, -s);
    }
    if (tid < 16) {
        float s, c;
        sincospif((float)tid / 32.0f, &s, &c);       // W_64^j
        sT16[tid] = make_float2(c, -s);
    }
    if (tid < 4) {
        float s, c;
        sincospif((float)tid / 8.0f, &s, &c);        // W_16^j == W^{1024j}
        sT4[tid] = make_float2(c, -s);
    }
    __syncthreads();

    // ================= h forward FFT -> sH (fp16) =================
    {
        const __half* hp = g_ht + (size_t)d * DIML;
        #pragma unroll
        for (int g = 0; g < 2; g++) {
            const int t = tid + 512 * g;
            float2 v[4][4];
            #pragma unroll
            for (int a = 0; a < 4; a++)
                #pragma unroll
                for (int b = 0; b < 4; b++)
                    v[a][b] = (a < 2)
                        ? make_float2(__half2float(hp[t + 1024 * b + 4096 * a]), 0.0f)
                        : make_float2(0.0f, 0.0f);
            passA_fwd(v, sA1024, sT4, t);
            #pragma unroll
            for (int a = 0; a < 4; a++)
                #pragma unroll
                for (int b = 0; b < 4; b++)
                    sA[SWZ(t + 1024 * b + 4096 * a)] = v[a][b];
        }
        __syncthreads();
        passB_fwd(sA, sW1024, sB256, tid);
        passB_fwd(sA, sW1024, sB256, tid + 512);
        __syncthreads();
        passC_fwd(sA, sT16, tid);
        passC_fwd(sA, sT16, tid + 512);
        __syncthreads();
        #pragma unroll
        for (int g = 0; g < 2; g++) {
            const int t = tid + 512 * g;
            float2 u16[16];
            #pragma unroll
            for (int j = 0; j < 16; j++) u16[j] = sA[SWZ(16 * t + j)];
            passD_fwd(u16, sT4);
            #pragma unroll
            for (int j = 0; j < 16; j++)
                sH[j * 1024 + t] = __floats2half2_rn(u16[j].x, u16[j].y);
        }
    }
    __syncthreads();              // all pass-D reads of sA done before x reuses it

    // ================= x forward FFT, * H, inverse FFT =================
    {
        const __half2* xp = g_xt + (size_t)d * DIML;
        #pragma unroll
        for (int g = 0; g < 2; g++) {
            const int t = tid + 512 * g;
            float2 v[4][4];
            #pragma unroll
            for (int a = 0; a < 4; a++)
                #pragma unroll
                for (int b = 0; b < 4; b++)
                    v[a][b] = (a < 2) ? __half22float2(xp[t + 1024 * b + 4096 * a])
                                      : make_float2(0.0f, 0.0f);
            passA_fwd(v, sA1024, sT4, t);
            #pragma unroll
            for (int a = 0; a < 4; a++)
                #pragma unroll
                for (int b = 0; b < 4; b++)
                    sA[SWZ(t + 1024 * b + 4096 * a)] = v[a][b];
        }
        __syncthreads();
        passB_fwd(sA, sW1024, sB256, tid);
        passB_fwd(sA, sW1024, sB256, tid + 512);
        __syncthreads();
        passC_fwd(sA, sT16, tid);
        passC_fwd(sA, sT16, tid + 512);
        __syncthreads();

        // pass D: fwd(4,1) + H multiply + inv(1,4)
        #pragma unroll
        for (int g = 0; g < 2; g++) {
            const int t = tid + 512 * g;
            float2 u16[16];
            #pragma unroll
            for (int j = 0; j < 16; j++) u16[j] = sA[SWZ(16 * t + j)];
            passD_fwd(u16, sT4);

            #pragma unroll
            for (int j = 0; j < 16; j++) {
                float2 hv = __half22float2(sH[j * 1024 + t]);
                u16[j] = cmul(u16[j], hv);
            }

            #pragma unroll
            for (int q = 0; q < 4; q++)
                ibfly(u16[4 * q], u16[4 * q + 1], u16[4 * q + 2], u16[4 * q + 3]);
            #pragma unroll
            for (int r = 0; r < 4; r++) {
                itw3(u16[r + 4], u16[r + 8], u16[r + 12], sT4[r]);
                ibfly(u16[r], u16[r + 4], u16[r + 8], u16[r + 12]);
            }
            #pragma unroll
            for (int j = 0; j < 16; j++) sA[SWZ(16 * t + j)] = u16[j];
        }
        __syncthreads();

        passC_inv(sA, sT16, tid);
        passC_inv(sA, sT16, tid + 512);
        __syncthreads();
        passB_inv(sA, sW1024, sB256, tid);
        passB_inv(sA, sW1024, sB256, tid + 512);
        __syncthreads();

        // pass A': inverse stages 1024 then 4096, scale + store
        const float scale = 1.0f / (float)NFFT;
        float2* yp = g_ys + (size_t)d * DIML;
        #pragma unroll
        for (int g = 0; g < 2; g++) {
            const int t = tid + 512 * g;
            float2 v[4][4];
            #pragma unroll
            for (int a = 0; a < 4; a++)
                #pragma unroll
                for (int b = 0; b < 4; b++)
                    v[a][b] = sA[SWZ(t + 1024 * b + 4096 * a)];
            const float2 at = sA1024[t];
            float2 w1 = cmul(at, at); w1 = cmul(w1, w1);   // at^4
            w1 = cconj(w1);
            float2 w2 = cmul(w1, w1), w3 = cmul(w1, w2);
            #pragma unroll
            for (int a = 0; a < 4; a++) {
                tw3w(v[a][1], v[a][2], v[a][3], w1, w2, w3);
                ibfly(v[a][0], v[a][1], v[a][2], v[a][3]);
            }
            #pragma unroll
            for (int b = 0; b < 4; b++) {
                float2 w = (b == 0) ? at : cmul(at, sT4[b]);
                itw3(v[1][b], v[2][b], v[3][b], w);
                ibfly(v[0][b], v[1][b], v[2][b], v[3][b]);
            }
            #pragma unroll
            for (int a = 0; a < 2; a++)
                #pragma unroll
                for (int b = 0; b < 4; b++) {
                    float2 r = v[a][b];
                    yp[t + 1024 * b + 4096 * a] = make_float2(r.x * scale, r.y * scale);
                }
        }
    }
}

// ---------------------------------------------------------------------------
extern "C" void kernel_launch(void* const* d_in, const int* in_sizes, int n_in,
                              void* d_out, int out_size) {
    const float* x    = (const float*)d_in[0];
    const float* h    = (const float*)d_in[1];
    const float* bias = (const float*)d_in[2];
    float* y = (float*)d_out;

    cudaFuncSetAttribute(fft_conv_fused_kernel,
                         cudaFuncAttributeMaxDynamicSharedMemorySize, SMEM_BYTES);

    transpose_in_kernel<<<dim3(DIMD / 32, DIML / 32, 2), dim3(32, 8)>>>(x, h);
    fft_conv_fused_kernel<<<DIMD, NT, SMEM_BYTES>>>();
    transpose_out_kernel<<<dim3(DIML / 32, DIMD / 32), dim3(32, 8)>>>(bias, y);
}

// round 13
// speedup vs baseline: 1.1560x; 1.0468x over previous
#include <cuda_runtime.h>
#include <cuda_fp16.h>
#include <cstdint>

#define NFFT 16384
#define DIML 8192
#define DIMD 1024
#define NT   512        // 512 threads, 2 groups of 16 elements per thread

// conflict-killing swizzle for sA: XOR low 4 bits with bits[7:4] (self-inverse)
#define SWZ(i) ((i) ^ (((i) >> 4) & 15))

// smem layout (bytes)
//   sA     : float2[16384]   @ 0        (131072)
//   sH     : half2 [16384]   @ 131072   (65536)
//   sA1024 : float2[1024]    @ 196608   (8192)   W^j,      j<1024 (W = W_16384)
//   sB256  : float2[256]     @ 204800   (2048)   W_256^j,  j<256   (stage-64 tw)
//   sW1024 : float2[256]     @ 206848   (2048)   W_1024^j, j<256   (stage-256 tw)
//   sT16   : float2[16]      @ 208896   (128)    W_64^j            (stage-16 tw)
//   sT4    : float2[4]       @ 209024   (32)     W_16^j == W^{1024j} (stage-4 + K4)
#define SMEM_BYTES 209056

// ---------------- device scratch ----------------
__device__ __half2 g_xt[(size_t)DIMD * DIML];      // transposed x, batches packed (fp16)
__device__ __half  g_ht[(size_t)DIMD * DIML];      // transposed h (fp16)
__device__ __half2 g_ys[(size_t)DIMD * DIML];      // transposed scaled output (fp16 pair)

__device__ __forceinline__ float2 cmul(float2 a, float2 b) {
    return make_float2(a.x * b.x - a.y * b.y, a.x * b.y + a.y * b.x);
}
__device__ __forceinline__ float2 cconj(float2 a) { return make_float2(a.x, -a.y); }
__device__ __forceinline__ float2 cadd(float2 a, float2 b) { return make_float2(a.x + b.x, a.y + b.y); }
__device__ __forceinline__ float2 csub(float2 a, float2 b) { return make_float2(a.x - b.x, a.y - b.y); }

// DIF forward radix-4 butterfly (in place)
__device__ __forceinline__ void bfly(float2& a, float2& b, float2& c, float2& d) {
    float2 t0 = cadd(a, c), t1 = csub(a, c), t2 = cadd(b, d), t3 = csub(b, d);
    float2 t3s = make_float2(t3.y, -t3.x);     // -i * t3
    a = cadd(t0, t2);
    c = csub(t0, t2);
    b = cadd(t1, t3s);
    d = csub(t1, t3s);
}
// inverse radix-4 butterfly (unnormalized)
__device__ __forceinline__ void ibfly(float2& a, float2& b, float2& c, float2& d) {
    float2 u0 = cadd(a, c), u1 = csub(a, c), u2 = cadd(b, d), u3 = csub(b, d);
    float2 u3s = make_float2(u3.y, -u3.x);
    a = cadd(u0, u2);
    c = csub(u0, u2);
    b = csub(u1, u3s);
    d = cadd(u1, u3s);
}
__device__ __forceinline__ void tw3w(float2& b, float2& c, float2& d,
                                     float2 w1, float2 w2, float2 w3) {
    b = cmul(b, w1); c = cmul(c, w2); d = cmul(d, w3);
}
__device__ __forceinline__ void tw3(float2& b, float2& c, float2& d, float2 w) {
    float2 w2 = cmul(w, w), w3 = cmul(w, w2);
    tw3w(b, c, d, w, w2, w3);
}
__device__ __forceinline__ void itw3(float2& b, float2& c, float2& d, float2 w) {
    float2 wc = cconj(w);
    float2 w2 = cmul(wc, wc), w3 = cmul(wc, w2);
    tw3w(b, c, d, wc, w2, w3);
}

// ---------------- transposes ----------------
// merged x/h input transpose: blockIdx.z = 0 -> x tile, 1 -> h tile
__global__ __launch_bounds__(256)
void transpose_in_kernel(const float* __restrict__ x, const float* __restrict__ h) {
    const int d0 = blockIdx.x * 32, n0 = blockIdx.y * 32;
    if (blockIdx.z == 0) {
        __shared__ float2 tile[32][33];
        for (int i = threadIdx.y; i < 32; i += 8) {
            const size_t base = (size_t)(n0 + i) * DIMD + d0 + threadIdx.x;
            tile[i][threadIdx.x] = make_float2(x[base], x[base + (size_t)DIML * DIMD]);
        }
        __syncthreads();
        for (int i = threadIdx.y; i < 32; i += 8) {
            float2 v = tile[threadIdx.x][i];
            g_xt[(size_t)(d0 + i) * DIML + n0 + threadIdx.x] =
                __floats2half2_rn(v.x, v.y);
        }
    } else {
        __shared__ float tileh[32][33];
        for (int i = threadIdx.y; i < 32; i += 8)
            tileh[i][threadIdx.x] = h[(size_t)(n0 + i) * DIMD + d0 + threadIdx.x];
        __syncthreads();
        for (int i = threadIdx.y; i < 32; i += 8)
            g_ht[(size_t)(d0 + i) * DIML + n0 + threadIdx.x] =
                __float2half_rn(tileh[threadIdx.x][i]);
    }
}

__global__ __launch_bounds__(256)
void transpose_out_kernel(const float* __restrict__ bias, float* __restrict__ y) {
    __shared__ __half2 tile[32][33];
    const int n0 = blockIdx.x * 32, d0 = blockIdx.y * 32;
    for (int i = threadIdx.y; i < 32; i += 8)
        tile[i][threadIdx.x] = g_ys[(size_t)(d0 + i) * DIML + n0 + threadIdx.x];
    __syncthreads();
    for (int i = threadIdx.y; i < 32; i += 8) {
        const int d = d0 + threadIdx.x;
        const int n = n0 + i;
        const float bv = __ldg(&bias[d]);
        const float2 v = __half22float2(tile[threadIdx.x][i]);
        y[(size_t)n * DIMD + d]          = v.x + bv;
        y[(size_t)(DIML + n) * DIMD + d] = v.y + bv;
    }
}

// ================= pass helpers =============================================

// Pass A: stages m=4096, m=1024 on v[a][b] (element t + 1024b + 4096a), t<1024
__device__ __forceinline__ void passA_fwd(float2 v[4][4], const float2* sA1024,
                                          const float2* sT4, int t) {
    const float2 at = sA1024[t];
    #pragma unroll
    for (int b = 0; b < 4; b++) {
        bfly(v[0][b], v[1][b], v[2][b], v[3][b]);
        float2 w = (b == 0) ? at : cmul(at, sT4[b]);   // W^{t+1024b}
        tw3(v[1][b], v[2][b], v[3][b], w);
    }
    float2 w1 = cmul(at, at); w1 = cmul(w1, w1);       // OT1024[t] = at^4
    float2 w2 = cmul(w1, w1), w3 = cmul(w1, w2);
    #pragma unroll
    for (int a = 0; a < 4; a++) {
        bfly(v[a][0], v[a][1], v[a][2], v[a][3]);
        tw3w(v[a][1], v[a][2], v[a][3], w1, w2, w3);
    }
}

// Pass B: stages m=256, m=64. element e(a,b) = u*1024 + rp + 64b + 256a
__device__ __forceinline__ void passB_fwd(float2* sA, const float2* sW1024,
                                          const float2* sB256, int t) {
    const int u = t >> 6, rp = t & 63;
    const int base = u * 1024 + rp;
    float2 v[4][4];
    #pragma unroll
    for (int a = 0; a < 4; a++)
        #pragma unroll
        for (int b = 0; b < 4; b++)
            v[a][b] = sA[SWZ(base + 64 * b + 256 * a)];
    #pragma unroll
    for (int b = 0; b < 4; b++) {
        bfly(v[0][b], v[1][b], v[2][b], v[3][b]);
        tw3(v[1][b], v[2][b], v[3][b], sW1024[rp + 64 * b]);
    }
    float2 w1 = sB256[rp];
    float2 w2 = cmul(w1, w1), w3 = cmul(w1, w2);
    #pragma unroll
    for (int a = 0; a < 4; a++) {
        bfly(v[a][0], v[a][1], v[a][2], v[a][3]);
        tw3w(v[a][1], v[a][2], v[a][3], w1, w2, w3);
    }
    #pragma unroll
    for (int a = 0; a < 4; a++)
        #pragma unroll
        for (int b = 0; b < 4; b++)
            sA[SWZ(base + 64 * b + 256 * a)] = v[a][b];
}

// Pass C: stage m=16. element e(s,a) = qb*64 + rq + 4096s + 16a
__device__ __forceinline__ void passC_fwd(float2* sA, const float2* sT16, int t) {
    const int rq = t & 15, qb = t >> 4;
    const int base = qb * 64 + rq;
    float2 v[4][4];
    #pragma unroll
    for (int s = 0; s < 4; s++)
        #pragma unroll
        for (int a = 0; a < 4; a++)
            v[s][a] = sA[SWZ(base + 4096 * s + 16 * a)];
    float2 w1 = sT16[rq];
    float2 w2 = cmul(w1, w1), w3 = cmul(w1, w2);
    #pragma unroll
    for (int s = 0; s < 4; s++) {
        bfly(v[s][0], v[s][1], v[s][2], v[s][3]);
        tw3w(v[s][1], v[s][2], v[s][3], w1, w2, w3);
    }
    #pragma unroll
    for (int s = 0; s < 4; s++)
        #pragma unroll
        for (int a = 0; a < 4; a++)
            sA[SWZ(base + 4096 * s + 16 * a)] = v[s][a];
}

// Pass D forward: stages m=4, m=1 on u16 (elements 16t..16t+15)
__device__ __forceinline__ void passD_fwd(float2 u16[16], const float2* sT4) {
    #pragma unroll
    for (int r = 0; r < 4; r++) {
        bfly(u16[r], u16[r + 4], u16[r + 8], u16[r + 12]);
        tw3(u16[r + 4], u16[r + 8], u16[r + 12], sT4[r]);
    }
    #pragma unroll
    for (int g = 0; g < 4; g++)
        bfly(u16[4 * g], u16[4 * g + 1], u16[4 * g + 2], u16[4 * g + 3]);
}

// inverse pass C'
__device__ __forceinline__ void passC_inv(float2* sA, const float2* sT16, int t) {
    const int rq = t & 15, qb = t >> 4;
    const int base = qb * 64 + rq;
    float2 w1 = cconj(sT16[rq]);
    float2 w2 = cmul(w1, w1), w3 = cmul(w1, w2);
    float2 v[4][4];
    #pragma unroll
    for (int s = 0; s < 4; s++)
        #pragma unroll
        for (int a = 0; a < 4; a++)
            v[s][a] = sA[SWZ(base + 4096 * s + 16 * a)];
    #pragma unroll
    for (int s = 0; s < 4; s++) {
        tw3w(v[s][1], v[s][2], v[s][3], w1, w2, w3);
        ibfly(v[s][0], v[s][1], v[s][2], v[s][3]);
    }
    #pragma unroll
    for (int s = 0; s < 4; s++)
        #pragma unroll
        for (int a = 0; a < 4; a++)
            sA[SWZ(base + 4096 * s + 16 * a)] = v[s][a];
}

// inverse pass B'
__device__ __forceinline__ void passB_inv(float2* sA, const float2* sW1024,
                                          const float2* sB256, int t) {
    const int u = t >> 6, rp = t & 63;
    const int base = u * 1024 + rp;
    float2 v[4][4];
    #pragma unroll
    for (int a = 0; a < 4; a++)
        #pragma unroll
        for (int b = 0; b < 4; b++)
            v[a][b] = sA[SWZ(base + 64 * b + 256 * a)];
    float2 w1 = cconj(sB256[rp]);
    float2 w2 = cmul(w1, w1), w3 = cmul(w1, w2);
    #pragma unroll
    for (int a = 0; a < 4; a++) {
        tw3w(v[a][1], v[a][2], v[a][3], w1, w2, w3);
        ibfly(v[a][0], v[a][1], v[a][2], v[a][3]);
    }
    #pragma unroll
    for (int b = 0; b < 4; b++) {
        itw3(v[1][b], v[2][b], v[3][b], sW1024[rp + 64 * b]);
        ibfly(v[0][b], v[1][b], v[2][b], v[3][b]);
    }
    #pragma unroll
    for (int a = 0; a < 4; a++)
        #pragma unroll
        for (int b = 0; b < 4; b++)
            sA[SWZ(base + 64 * b + 256 * a)] = v[a][b];
}

// ================= fused conv: h-FFT (H -> smem fp16) + x-FFT + inv =========
__global__ __launch_bounds__(NT, 1)
void fft_conv_fused_kernel() {
    extern __shared__ char smem[];
    float2* sA     = (float2*)(smem);
    __half2* sH    = (__half2*)(smem + 131072);
    float2* sA1024 = (float2*)(smem + 196608);
    float2* sB256  = (float2*)(smem + 204800);
    float2* sW1024 = (float2*)(smem + 206848);
    float2* sT16   = (float2*)(smem + 208896);
    float2* sT4    = (float2*)(smem + 209024);

    const int tid = threadIdx.x, d = blockIdx.x;

    // ---- table init ----
    for (int j = tid; j < 1024; j += NT) {
        float s, c;
        sincospif((float)j / 8192.0f, &s, &c);       // W^j
        sA1024[j] = make_float2(c, -s);
    }
    if (tid < 256) {
        float s, c;
        sincospif((float)tid / 128.0f, &s, &c);      // W_256^j
        sB256[tid] = make_float2(c, -s);
        sincospif((float)tid / 512.0f, &s, &c);      // W_1024^j
        sW1024[tid] = make_float2(c, -s);
    }
    if (tid < 16) {
        float s, c;
        sincospif((float)tid / 32.0f, &s, &c);       // W_64^j
        sT16[tid] = make_float2(c, -s);
    }
    if (tid < 4) {
        float s, c;
        sincospif((float)tid / 8.0f, &s, &c);        // W_16^j == W^{1024j}
        sT4[tid] = make_float2(c, -s);
    }
    __syncthreads();

    // ================= h forward FFT -> sH (fp16) =================
    {
        const __half* hp = g_ht + (size_t)d * DIML;
        #pragma unroll
        for (int g = 0; g < 2; g++) {
            const int t = tid + 512 * g;
            float2 v[4][4];
            #pragma unroll
            for (int a = 0; a < 4; a++)
                #pragma unroll
                for (int b = 0; b < 4; b++)
                    v[a][b] = (a < 2)
                        ? make_float2(__half2float(hp[t + 1024 * b + 4096 * a]), 0.0f)
                        : make_float2(0.0f, 0.0f);
            passA_fwd(v, sA1024, sT4, t);
            #pragma unroll
            for (int a = 0; a < 4; a++)
                #pragma unroll
                for (int b = 0; b < 4; b++)
                    sA[SWZ(t + 1024 * b + 4096 * a)] = v[a][b];
        }
        __syncthreads();
        passB_fwd(sA, sW1024, sB256, tid);
        passB_fwd(sA, sW1024, sB256, tid + 512);
        __syncthreads();
        passC_fwd(sA, sT16, tid);
        passC_fwd(sA, sT16, tid + 512);
        __syncthreads();
        #pragma unroll
        for (int g = 0; g < 2; g++) {
            const int t = tid + 512 * g;
            float2 u16[16];
            #pragma unroll
            for (int j = 0; j < 16; j++) u16[j] = sA[SWZ(16 * t + j)];
            passD_fwd(u16, sT4);
            #pragma unroll
            for (int j = 0; j < 16; j++)
                sH[j * 1024 + t] = __floats2half2_rn(u16[j].x, u16[j].y);
        }
    }
    __syncthreads();              // all pass-D reads of sA done before x reuses it

    // ================= x forward FFT, * H, inverse FFT =================
    {
        const __half2* xp = g_xt + (size_t)d * DIML;
        #pragma unroll
        for (int g = 0; g < 2; g++) {
            const int t = tid + 512 * g;
            float2 v[4][4];
            #pragma unroll
            for (int a = 0; a < 4; a++)
                #pragma unroll
                for (int b = 0; b < 4; b++)
                    v[a][b] = (a < 2) ? __half22float2(xp[t + 1024 * b + 4096 * a])
                                      : make_float2(0.0f, 0.0f);
            passA_fwd(v, sA1024, sT4, t);
            #pragma unroll
            for (int a = 0; a < 4; a++)
                #pragma unroll
                for (int b = 0; b < 4; b++)
                    sA[SWZ(t + 1024 * b + 4096 * a)] = v[a][b];
        }
        __syncthreads();
        passB_fwd(sA, sW1024, sB256, tid);
        passB_fwd(sA, sW1024, sB256, tid + 512);
        __syncthreads();
        passC_fwd(sA, sT16, tid);
        passC_fwd(sA, sT16, tid + 512);
        __syncthreads();

        // pass D: fwd(4,1) + H multiply + inv(1,4)
        #pragma unroll
        for (int g = 0; g < 2; g++) {
            const int t = tid + 512 * g;
            float2 u16[16];
            #pragma unroll
            for (int j = 0; j < 16; j++) u16[j] = sA[SWZ(16 * t + j)];
            passD_fwd(u16, sT4);

            #pragma unroll
            for (int j = 0; j < 16; j++) {
                float2 hv = __half22float2(sH[j * 1024 + t]);
                u16[j] = cmul(u16[j], hv);
            }

            #pragma unroll
            for (int q = 0; q < 4; q++)
                ibfly(u16[4 * q], u16[4 * q + 1], u16[4 * q + 2], u16[4 * q + 3]);
            #pragma unroll
            for (int r = 0; r < 4; r++) {
                itw3(u16[r + 4], u16[r + 8], u16[r + 12], sT4[r]);
                ibfly(u16[r], u16[r + 4], u16[r + 8], u16[r + 12]);
            }
            #pragma unroll
            for (int j = 0; j < 16; j++) sA[SWZ(16 * t + j)] = u16[j];
        }
        __syncthreads();

        passC_inv(sA, sT16, tid);
        passC_inv(sA, sT16, tid + 512);
        __syncthreads();
        passB_inv(sA, sW1024, sB256, tid);
        passB_inv(sA, sW1024, sB256, tid + 512);
        __syncthreads();

        // pass A': inverse stages 1024 then 4096, scale + store (fp16 staging)
        const float scale = 1.0f / (float)NFFT;
        __half2* yp = g_ys + (size_t)d * DIML;
        #pragma unroll
        for (int g = 0; g < 2; g++) {
            const int t = tid + 512 * g;
            float2 v[4][4];
            #pragma unroll
            for (int a = 0; a < 4; a++)
                #pragma unroll
                for (int b = 0; b < 4; b++)
                    v[a][b] = sA[SWZ(t + 1024 * b + 4096 * a)];
            const float2 at = sA1024[t];
            float2 w1 = cmul(at, at); w1 = cmul(w1, w1);   // at^4
            w1 = cconj(w1);
            float2 w2 = cmul(w1, w1), w3 = cmul(w1, w2);
            #pragma unroll
            for (int a = 0; a < 4; a++) {
                tw3w(v[a][1], v[a][2], v[a][3], w1, w2, w3);
                ibfly(v[a][0], v[a][1], v[a][2], v[a][3]);
            }
            #pragma unroll
            for (int b = 0; b < 4; b++) {
                float2 w = (b == 0) ? at : cmul(at, sT4[b]);
                itw3(v[1][b], v[2][b], v[3][b], w);
                ibfly(v[0][b], v[1][b], v[2][b], v[3][b]);
            }
            #pragma unroll
            for (int a = 0; a < 2; a++)
                #pragma unroll
                for (int b = 0; b < 4; b++) {
                    float2 r = v[a][b];
                    yp[t + 1024 * b + 4096 * a] =
                        __floats2half2_rn(r.x * scale, r.y * scale);
                }
        }
    }
}

// ---------------------------------------------------------------------------
extern "C" void kernel_launch(void* const* d_in, const int* in_sizes, int n_in,
                              void* d_out, int out_size) {
    const float* x    = (const float*)d_in[0];
    const float* h    = (const float*)d_in[1];
    const float* bias = (const float*)d_in[2];
    float* y = (float*)d_out;

    cudaFuncSetAttribute(fft_conv_fused_kernel,
                         cudaFuncAttributeMaxDynamicSharedMemorySize, SMEM_BYTES);

    transpose_in_kernel<<<dim3(DIMD / 32, DIML / 32, 2), dim3(32, 8)>>>(x, h);
    fft_conv_fused_kernel<<<DIMD, NT, SMEM_BYTES>>>();
    transpose_out_kernel<<<dim3(DIML / 32, DIMD / 32), dim3(32, 8)>>>(bias, y);
}

// round 14
// speedup vs baseline: 1.2604x; 1.0903x over previous
#include <cuda_runtime.h>
#include <cuda_fp16.h>
#include <cstdint>

#define NFFT 16384
#define DIML 8192
#define DIMD 1024
#define NT   512        // 512 threads, 2 groups of 16 elements per thread

// conflict-killing swizzle for sA: XOR low 4 bits with bits[7:4] (self-inverse)
#define SWZ(i) ((i) ^ (((i) >> 4) & 15))

// smem layout (bytes)
//   sA     : float2[16384]   @ 0        (131072)
//   sH     : half2 [16384]   @ 131072   (65536)
//   sA1024 : float2[1024]    @ 196608   (8192)   W^j,      j<1024 (W = W_16384)
//   sB256  : float2[256]     @ 204800   (2048)   W_256^j,  j<256   (stage-64 tw)
//   sW1024 : float2[256]     @ 206848   (2048)   W_1024^j, j<256   (stage-256 tw)
//   sT16   : float2[16]      @ 208896   (128)    W_64^j            (stage-16 tw)
//   sT4    : float2[4]       @ 209024   (32)     W_16^j == W^{1024j} (stage-4 + K4)
#define SMEM_BYTES 209056

// ---------------- device scratch ----------------
__device__ __half2 g_xt[(size_t)DIMD * DIML];      // transposed x, batches packed (fp16)
__device__ __half  g_ht[(size_t)DIMD * DIML];      // transposed h (fp16)
__device__ __half2 g_ys[(size_t)DIMD * DIML];      // transposed scaled output (fp16 pair)

__device__ __forceinline__ float2 cmul(float2 a, float2 b) {
    return make_float2(a.x * b.x - a.y * b.y, a.x * b.y + a.y * b.x);
}
__device__ __forceinline__ float2 cconj(float2 a) { return make_float2(a.x, -a.y); }
__device__ __forceinline__ float2 cadd(float2 a, float2 b) { return make_float2(a.x + b.x, a.y + b.y); }
__device__ __forceinline__ float2 csub(float2 a, float2 b) { return make_float2(a.x - b.x, a.y - b.y); }

// DIF forward radix-4 butterfly (in place)
__device__ __forceinline__ void bfly(float2& a, float2& b, float2& c, float2& d) {
    float2 t0 = cadd(a, c), t1 = csub(a, c), t2 = cadd(b, d), t3 = csub(b, d);
    float2 t3s = make_float2(t3.y, -t3.x);     // -i * t3
    a = cadd(t0, t2);
    c = csub(t0, t2);
    b = cadd(t1, t3s);
    d = csub(t1, t3s);
}
// inverse radix-4 butterfly (unnormalized)
__device__ __forceinline__ void ibfly(float2& a, float2& b, float2& c, float2& d) {
    float2 u0 = cadd(a, c), u1 = csub(a, c), u2 = cadd(b, d), u3 = csub(b, d);
    float2 u3s = make_float2(u3.y, -u3.x);
    a = cadd(u0, u2);
    c = csub(u0, u2);
    b = csub(u1, u3s);
    d = cadd(u1, u3s);
}
__device__ __forceinline__ void tw3w(float2& b, float2& c, float2& d,
                                     float2 w1, float2 w2, float2 w3) {
    b = cmul(b, w1); c = cmul(c, w2); d = cmul(d, w3);
}
__device__ __forceinline__ void tw3(float2& b, float2& c, float2& d, float2 w) {
    float2 w2 = cmul(w, w), w3 = cmul(w, w2);
    tw3w(b, c, d, w, w2, w3);
}
__device__ __forceinline__ void itw3(float2& b, float2& c, float2& d, float2 w) {
    float2 wc = cconj(w);
    float2 w2 = cmul(wc, wc), w3 = cmul(wc, w2);
    tw3w(b, c, d, wc, w2, w3);
}

// ---------------- transposes ----------------
// merged vectorized x/h input transpose: blockIdx.z = 0 -> x tile, 1 -> h tile
// block (8, 32): thread (tx, ty) covers a 4-wide slice.
__global__ __launch_bounds__(256)
void transpose_in_kernel(const float* __restrict__ x, const float* __restrict__ h) {
    const int d0 = blockIdx.x * 32, n0 = blockIdx.y * 32;
    const int tx = threadIdx.x, ty = threadIdx.y;
    if (blockIdx.z == 0) {
        __shared__ float2 tile[32][33];   // [n_local][d_local]
        // load: row n0+ty, cols d0+4tx..+3, both batches, pack (x0,x1)
        const size_t base = (size_t)(n0 + ty) * DIMD + d0 + 4 * tx;
        const float4 v0 = *reinterpret_cast<const float4*>(&x[base]);
        const float4 v1 = *reinterpret_cast<const float4*>(&x[base + (size_t)DIML * DIMD]);
        tile[ty][4 * tx + 0] = make_float2(v0.x, v1.x);
        tile[ty][4 * tx + 1] = make_float2(v0.y, v1.y);
        tile[ty][4 * tx + 2] = make_float2(v0.z, v1.z);
        tile[ty][4 * tx + 3] = make_float2(v0.w, v1.w);
        __syncthreads();
        // store: d = d0+ty, n = n0+4tx..+3  (4 half2 = 16 B vector store)
        __half2 o[4];
        #pragma unroll
        for (int k = 0; k < 4; k++) {
            float2 v = tile[4 * tx + k][ty];
            o[k] = __floats2half2_rn(v.x, v.y);
        }
        *reinterpret_cast<uint4*>(&g_xt[(size_t)(d0 + ty) * DIML + n0 + 4 * tx]) =
            *reinterpret_cast<const uint4*>(o);
    } else {
        __shared__ float tileh[32][33];
        const size_t base = (size_t)(n0 + ty) * DIMD + d0 + 4 * tx;
        const float4 v = *reinterpret_cast<const float4*>(&h[base]);
        tileh[ty][4 * tx + 0] = v.x;
        tileh[ty][4 * tx + 1] = v.y;
        tileh[ty][4 * tx + 2] = v.z;
        tileh[ty][4 * tx + 3] = v.w;
        __syncthreads();
        __half o[4];
        #pragma unroll
        for (int k = 0; k < 4; k++)
            o[k] = __float2half_rn(tileh[4 * tx + k][ty]);
        *reinterpret_cast<uint2*>(&g_ht[(size_t)(d0 + ty) * DIML + n0 + 4 * tx]) =
            *reinterpret_cast<const uint2*>(o);
    }
}

__global__ __launch_bounds__(256)
void transpose_out_kernel(const float* __restrict__ bias, float* __restrict__ y) {
    __shared__ __half2 tile[32][33];
    const int n0 = blockIdx.x * 32, d0 = blockIdx.y * 32;
    for (int i = threadIdx.y; i < 32; i += 8)
        tile[i][threadIdx.x] = g_ys[(size_t)(d0 + i) * DIML + n0 + threadIdx.x];
    __syncthreads();
    for (int i = threadIdx.y; i < 32; i += 8) {
        const int d = d0 + threadIdx.x;
        const int n = n0 + i;
        const float bv = __ldg(&bias[d]);
        const float2 v = __half22float2(tile[threadIdx.x][i]);
        y[(size_t)n * DIMD + d]          = v.x + bv;
        y[(size_t)(DIML + n) * DIMD + d] = v.y + bv;
    }
}

// ================= pass helpers =============================================

// Pass A: stages m=4096, m=1024 on v[a][b] (element t + 1024b + 4096a), t<1024
__device__ __forceinline__ void passA_fwd(float2 v[4][4], const float2* sA1024,
                                          const float2* sT4, int t) {
    const float2 at = sA1024[t];
    #pragma unroll
    for (int b = 0; b < 4; b++) {
        bfly(v[0][b], v[1][b], v[2][b], v[3][b]);
        float2 w = (b == 0) ? at : cmul(at, sT4[b]);   // W^{t+1024b}
        tw3(v[1][b], v[2][b], v[3][b], w);
    }
    float2 w1 = cmul(at, at); w1 = cmul(w1, w1);       // OT1024[t] = at^4
    float2 w2 = cmul(w1, w1), w3 = cmul(w1, w2);
    #pragma unroll
    for (int a = 0; a < 4; a++) {
        bfly(v[a][0], v[a][1], v[a][2], v[a][3]);
        tw3w(v[a][1], v[a][2], v[a][3], w1, w2, w3);
    }
}

// Pass B: stages m=256, m=64. element e(a,b) = u*1024 + rp + 64b + 256a
__device__ __forceinline__ void passB_fwd(float2* sA, const float2* sW1024,
                                          const float2* sB256, int t) {
    const int u = t >> 6, rp = t & 63;
    const int base = u * 1024 + rp;
    float2 v[4][4];
    #pragma unroll
    for (int a = 0; a < 4; a++)
        #pragma unroll
        for (int b = 0; b < 4; b++)
            v[a][b] = sA[SWZ(base + 64 * b + 256 * a)];
    #pragma unroll
    for (int b = 0; b < 4; b++) {
        bfly(v[0][b], v[1][b], v[2][b], v[3][b]);
        tw3(v[1][b], v[2][b], v[3][b], sW1024[rp + 64 * b]);
    }
    float2 w1 = sB256[rp];
    float2 w2 = cmul(w1, w1), w3 = cmul(w1, w2);
    #pragma unroll
    for (int a = 0; a < 4; a++) {
        bfly(v[a][0], v[a][1], v[a][2], v[a][3]);
        tw3w(v[a][1], v[a][2], v[a][3], w1, w2, w3);
    }
    #pragma unroll
    for (int a = 0; a < 4; a++)
        #pragma unroll
        for (int b = 0; b < 4; b++)
            sA[SWZ(base + 64 * b + 256 * a)] = v[a][b];
}

// Pass C: stage m=16. element e(s,a) = qb*64 + rq + 4096s + 16a
__device__ __forceinline__ void passC_fwd(float2* sA, const float2* sT16, int t) {
    const int rq = t & 15, qb = t >> 4;
    const int base = qb * 64 + rq;
    float2 v[4][4];
    #pragma unroll
    for (int s = 0; s < 4; s++)
        #pragma unroll
        for (int a = 0; a < 4; a++)
            v[s][a] = sA[SWZ(base + 4096 * s + 16 * a)];
    float2 w1 = sT16[rq];
    float2 w2 = cmul(w1, w1), w3 = cmul(w1, w2);
    #pragma unroll
    for (int s = 0; s < 4; s++) {
        bfly(v[s][0], v[s][1], v[s][2], v[s][3]);
        tw3w(v[s][1], v[s][2], v[s][3], w1, w2, w3);
    }
    #pragma unroll
    for (int s = 0; s < 4; s++)
        #pragma unroll
        for (int a = 0; a < 4; a++)
            sA[SWZ(base + 4096 * s + 16 * a)] = v[s][a];
}

// Pass D forward: stages m=4, m=1 on u16 (elements 16t..16t+15)
__device__ __forceinline__ void passD_fwd(float2 u16[16], const float2* sT4) {
    #pragma unroll
    for (int r = 0; r < 4; r++) {
        bfly(u16[r], u16[r + 4], u16[r + 8], u16[r + 12]);
        tw3(u16[r + 4], u16[r + 8], u16[r + 12], sT4[r]);
    }
    #pragma unroll
    for (int g = 0; g < 4; g++)
        bfly(u16[4 * g], u16[4 * g + 1], u16[4 * g + 2], u16[4 * g + 3]);
}

// inverse pass C'
__device__ __forceinline__ void passC_inv(float2* sA, const float2* sT16, int t) {
    const int rq = t & 15, qb = t >> 4;
    const int base = qb * 64 + rq;
    float2 w1 = cconj(sT16[rq]);
    float2 w2 = cmul(w1, w1), w3 = cmul(w1, w2);
    float2 v[4][4];
    #pragma unroll
    for (int s = 0; s < 4; s++)
        #pragma unroll
        for (int a = 0; a < 4; a++)
            v[s][a] = sA[SWZ(base + 4096 * s + 16 * a)];
    #pragma unroll
    for (int s = 0; s < 4; s++) {
        tw3w(v[s][1], v[s][2], v[s][3], w1, w2, w3);
        ibfly(v[s][0], v[s][1], v[s][2], v[s][3]);
    }
    #pragma unroll
    for (int s = 0; s < 4; s++)
        #pragma unroll
        for (int a = 0; a < 4; a++)
            sA[SWZ(base + 4096 * s + 16 * a)] = v[s][a];
}

// inverse pass B'
__device__ __forceinline__ void passB_inv(float2* sA, const float2* sW1024,
                                          const float2* sB256, int t) {
    const int u = t >> 6, rp = t & 63;
    const int base = u * 1024 + rp;
    float2 v[4][4];
    #pragma unroll
    for (int a = 0; a < 4; a++)
        #pragma unroll
        for (int b = 0; b < 4; b++)
            v[a][b] = sA[SWZ(base + 64 * b + 256 * a)];
    float2 w1 = cconj(sB256[rp]);
    float2 w2 = cmul(w1, w1), w3 = cmul(w1, w2);
    #pragma unroll
    for (int a = 0; a < 4; a++) {
        tw3w(v[a][1], v[a][2], v[a][3], w1, w2, w3);
        ibfly(v[a][0], v[a][1], v[a][2], v[a][3]);
    }
    #pragma unroll
    for (int b = 0; b < 4; b++) {
        itw3(v[1][b], v[2][b], v[3][b], sW1024[rp + 64 * b]);
        ibfly(v[0][b], v[1][b], v[2][b], v[3][b]);
    }
    #pragma unroll
    for (int a = 0; a < 4; a++)
        #pragma unroll
        for (int b = 0; b < 4; b++)
            sA[SWZ(base + 64 * b + 256 * a)] = v[a][b];
}

// ================= fused conv: h-FFT (H -> smem fp16) + x-FFT + inv =========
__global__ __launch_bounds__(NT, 1)
void fft_conv_fused_kernel() {
    extern __shared__ char smem[];
    float2* sA     = (float2*)(smem);
    __half2* sH    = (__half2*)(smem + 131072);
    float2* sA1024 = (float2*)(smem + 196608);
    float2* sB256  = (float2*)(smem + 204800);
    float2* sW1024 = (float2*)(smem + 206848);
    float2* sT16   = (float2*)(smem + 208896);
    float2* sT4    = (float2*)(smem + 209024);

    const int tid = threadIdx.x, d = blockIdx.x;

    // ---- table init ----
    for (int j = tid; j < 1024; j += NT) {
        float s, c;
        sincospif((float)j / 8192.0f, &s, &c);       // W^j
        sA1024[j] = make_float2(c, -s);
    }
    if (tid < 256) {
        float s, c;
        sincospif((float)tid / 128.0f, &s, &c);      // W_256^j
        sB256[tid] = make_float2(c, -s);
        sincospif((float)tid / 512.0f, &s, &c);      // W_1024^j
        sW1024[tid] = make_float2(c, -s);
    }
    if (tid < 16) {
        float s, c;
        sincospif((float)tid / 32.0f, &s, &c);       // W_64^j
        sT16[tid] = make_float2(c, -s);
    }
    if (tid < 4) {
        float s, c;
        sincospif((float)tid / 8.0f, &s, &c);        // W_16^j == W^{1024j}
        sT4[tid] = make_float2(c, -s);
    }
    __syncthreads();

    // ================= h forward FFT -> sH (fp16) =================
    {
        const __half* hp = g_ht + (size_t)d * DIML;
        #pragma unroll
        for (int g = 0; g < 2; g++) {
            const int t = tid + 512 * g;
            float2 v[4][4];
            #pragma unroll
            for (int a = 0; a < 4; a++)
                #pragma unroll
                for (int b = 0; b < 4; b++)
                    v[a][b] = (a < 2)
                        ? make_float2(__half2float(hp[t + 1024 * b + 4096 * a]), 0.0f)
                        : make_float2(0.0f, 0.0f);
            passA_fwd(v, sA1024, sT4, t);
            #pragma unroll
            for (int a = 0; a < 4; a++)
                #pragma unroll
                for (int b = 0; b < 4; b++)
                    sA[SWZ(t + 1024 * b + 4096 * a)] = v[a][b];
        }
        __syncthreads();
        passB_fwd(sA, sW1024, sB256, tid);
        passB_fwd(sA, sW1024, sB256, tid + 512);
        __syncthreads();
        passC_fwd(sA, sT16, tid);
        passC_fwd(sA, sT16, tid + 512);
        __syncthreads();
        #pragma unroll
        for (int g = 0; g < 2; g++) {
            const int t = tid + 512 * g;
            float2 u16[16];
            #pragma unroll
            for (int j = 0; j < 16; j++) u16[j] = sA[SWZ(16 * t + j)];
            passD_fwd(u16, sT4);
            #pragma unroll
            for (int j = 0; j < 16; j++)
                sH[j * 1024 + t] = __floats2half2_rn(u16[j].x, u16[j].y);
        }
    }
    __syncthreads();              // all pass-D reads of sA done before x reuses it

    // ================= x forward FFT, * H, inverse FFT =================
    {
        const __half2* xp = g_xt + (size_t)d * DIML;
        #pragma unroll
        for (int g = 0; g < 2; g++) {
            const int t = tid + 512 * g;
            float2 v[4][4];
            #pragma unroll
            for (int a = 0; a < 4; a++)
                #pragma unroll
                for (int b = 0; b < 4; b++)
                    v[a][b] = (a < 2) ? __half22float2(xp[t + 1024 * b + 4096 * a])
                                      : make_float2(0.0f, 0.0f);
            passA_fwd(v, sA1024, sT4, t);
            #pragma unroll
            for (int a = 0; a < 4; a++)
                #pragma unroll
                for (int b = 0; b < 4; b++)
                    sA[SWZ(t + 1024 * b + 4096 * a)] = v[a][b];
        }
        __syncthreads();
        passB_fwd(sA, sW1024, sB256, tid);
        passB_fwd(sA, sW1024, sB256, tid + 512);
        __syncthreads();
        passC_fwd(sA, sT16, tid);
        passC_fwd(sA, sT16, tid + 512);
        __syncthreads();

        // pass D: fwd(4,1) + H multiply + inv(1,4)
        #pragma unroll
        for (int g = 0; g < 2; g++) {
            const int t = tid + 512 * g;
            float2 u16[16];
            #pragma unroll
            for (int j = 0; j < 16; j++) u16[j] = sA[SWZ(16 * t + j)];
            passD_fwd(u16, sT4);

            #pragma unroll
            for (int j = 0; j < 16; j++) {
                float2 hv = __half22float2(sH[j * 1024 + t]);
                u16[j] = cmul(u16[j], hv);
            }

            #pragma unroll
            for (int q = 0; q < 4; q++)
                ibfly(u16[4 * q], u16[4 * q + 1], u16[4 * q + 2], u16[4 * q + 3]);
            #pragma unroll
            for (int r = 0; r < 4; r++) {
                itw3(u16[r + 4], u16[r + 8], u16[r + 12], sT4[r]);
                ibfly(u16[r], u16[r + 4], u16[r + 8], u16[r + 12]);
            }
            #pragma unroll
            for (int j = 0; j < 16; j++) sA[SWZ(16 * t + j)] = u16[j];
        }
        __syncthreads();

        passC_inv(sA, sT16, tid);
        passC_inv(sA, sT16, tid + 512);
        __syncthreads();
        passB_inv(sA, sW1024, sB256, tid);
        passB_inv(sA, sW1024, sB256, tid + 512);
        __syncthreads();

        // pass A': inverse stages 1024 then 4096, scale + store (fp16 staging)
        const float scale = 1.0f / (float)NFFT;
        __half2* yp = g_ys + (size_t)d * DIML;
        #pragma unroll
        for (int g = 0; g < 2; g++) {
            const int t = tid + 512 * g;
            float2 v[4][4];
            #pragma unroll
            for (int a = 0; a < 4; a++)
                #pragma unroll
                for (int b = 0; b < 4; b++)
                    v[a][b] = sA[SWZ(t + 1024 * b + 4096 * a)];
            const float2 at = sA1024[t];
            float2 w1 = cmul(at, at); w1 = cmul(w1, w1);   // at^4
            w1 = cconj(w1);
            float2 w2 = cmul(w1, w1), w3 = cmul(w1, w2);
            #pragma unroll
            for (int a = 0; a < 4; a++) {
                tw3w(v[a][1], v[a][2], v[a][3], w1, w2, w3);
                ibfly(v[a][0], v[a][1], v[a][2], v[a][3]);
            }
            #pragma unroll
            for (int b = 0; b < 4; b++) {
                float2 w = (b == 0) ? at : cmul(at, sT4[b]);
                itw3(v[1][b], v[2][b], v[3][b], w);
                ibfly(v[0][b], v[1][b], v[2][b], v[3][b]);
            }
            #pragma unroll
            for (int a = 0; a < 2; a++)
                #pragma unroll
                for (int b = 0; b < 4; b++) {
                    float2 r = v[a][b];
                    yp[t + 1024 * b + 4096 * a] =
                        __floats2half2_rn(r.x * scale, r.y * scale);
                }
        }
    }
}

// ---------------------------------------------------------------------------
extern "C" void kernel_launch(void* const* d_in, const int* in_sizes, int n_in,
                              void* d_out, int out_size) {
    const float* x    = (const float*)d_in[0];
    const float* h    = (const float*)d_in[1];
    const float* bias = (const float*)d_in[2];
    float* y = (float*)d_out;

    cudaFuncSetAttribute(fft_conv_fused_kernel,
                         cudaFuncAttributeMaxDynamicSharedMemorySize, SMEM_BYTES);

    transpose_in_kernel<<<dim3(DIMD / 32, DIML / 32, 2), dim3(8, 32)>>>(x, h);
    fft_conv_fused_kernel<<<DIMD, NT, SMEM_BYTES>>>();
    transpose_out_kernel<<<dim3(DIML / 32, DIMD / 32), dim3(32, 8)>>>(bias, y);
}